// round 1
// baseline (speedup 1.0000x reference)
#include <cuda_runtime.h>
#include <math.h>

#define BB 4096
#define TT 70
#define EE 300
#define HH 60
#define RR (BB*TT)   // 286720 rows

// ---------------- scratch (static device memory; no allocations) ----------------
__device__ float g_gi_lstm[RR*480];   // [T][B][480]  (fwd gates 0..239, bwd 240..479)
__device__ float g_h_lstm [RR*120];   // [T][B][120]  (fwd 0..59, bwd 60..119)
__device__ float g_gi_gru [RR*360];   // [T][B][360]  (fwd 0..179, bwd 180..359)
__device__ float g_h_gru  [RR*120];   // [B][T][120]
__device__ float g_ghf    [BB*HH];
__device__ float g_ghb    [BB*HH];

__device__ __forceinline__ float sigf(float x) { return 1.f / (1.f + __expf(-x)); }

// ---------------- GEMM: C[r][n] = sum_k A[r][k] * W[n][k] + bias[n] ----------------
// MODE 0: A = emb[tokens] gathered (K=300), W = [lstm_Wih_f; lstm_Wih_b] (N=480) -> g_gi_lstm
// MODE 1: A = g_h_lstm (K=120),            W = [gru_Wih_f;  gru_Wih_b ] (N=360) -> g_gi_gru
template<int MODE>
__global__ __launch_bounds__(256) void gemm_k(
    const float* __restrict__ emb, const int* __restrict__ tokens,
    const float* __restrict__ W0, const float* __restrict__ W1,
    const float* __restrict__ bias0, const float* __restrict__ bias1)
{
    constexpr int N  = (MODE == 0) ? 480 : 360;
    constexpr int K  = (MODE == 0) ? 300 : 120;
    constexpr int NS = (MODE == 0) ? 240 : 180;
    constexpr int TM = 128, TN = 96, TK = 20;

    __shared__ float Ash[TK][TM + 1];
    __shared__ float Bsh[TK][TN + 1];
    __shared__ int rbase[TM];

    float* __restrict__ C = (MODE == 0) ? g_gi_lstm : g_gi_gru;
    const float* __restrict__ A = (MODE == 0) ? emb : (const float*)g_h_lstm;

    const int m0 = blockIdx.x * TM;
    const int n0 = blockIdx.y * TN;
    const int tid = threadIdx.x;

    for (int i = tid; i < TM; i += 256) {
        int r = m0 + i;
        if (MODE == 0) {
            int t = r >> 12;          // r = t*B + b, B = 4096
            int b = r & (BB - 1);
            rbase[i] = tokens[b * TT + t] * K;
        } else {
            rbase[i] = r * K;
        }
    }

    float acc[8][6];
    #pragma unroll
    for (int i = 0; i < 8; i++)
        #pragma unroll
        for (int j = 0; j < 6; j++) acc[i][j] = 0.f;

    const int tx = tid & 15;   // 16 cols of threads -> 6 n each
    const int ty = tid >> 4;   // 16 rows of threads -> 8 m each
    __syncthreads();

    for (int k0 = 0; k0 < K; k0 += TK) {
        // A tile: TM*TK = 2560 = 10 * 256
        #pragma unroll
        for (int it = 0; it < (TM * TK) / 256; it++) {
            int i = tid + it * 256;
            int m = i / TK, kk = i - m * TK;
            Ash[kk][m] = A[rbase[m] + k0 + kk];
        }
        // B tile: TK*TN = 1920
        for (int i = tid; i < TK * TN; i += 256) {
            int n = i / TK, kk = i - n * TK;
            int ng = n0 + n;
            float v = 0.f;
            if (ng < N)
                v = (ng < NS) ? W0[ng * K + k0 + kk] : W1[(ng - NS) * K + k0 + kk];
            Bsh[kk][n] = v;
        }
        __syncthreads();
        #pragma unroll
        for (int kk = 0; kk < TK; kk++) {
            float a[8], bv[6];
            #pragma unroll
            for (int i = 0; i < 8; i++) a[i] = Ash[kk][ty * 8 + i];
            #pragma unroll
            for (int j = 0; j < 6; j++) bv[j] = Bsh[kk][tx * 6 + j];
            #pragma unroll
            for (int i = 0; i < 8; i++)
                #pragma unroll
                for (int j = 0; j < 6; j++)
                    acc[i][j] = fmaf(a[i], bv[j], acc[i][j]);
        }
        __syncthreads();
    }

    #pragma unroll
    for (int j = 0; j < 6; j++) {
        int ng = n0 + tx * 6 + j;
        if (ng < N) {
            float bv = (ng < NS) ? bias0[ng] : bias1[ng - NS];
            #pragma unroll
            for (int i = 0; i < 8; i++)
                C[(size_t)(m0 + ty * 8 + i) * N + ng] = acc[i][j] + bv;
        }
    }
}

// ---------------- LSTM recurrence (both directions; 32-batch tiles) ----------------
// blockIdx.x: bit0 = dir, rest = batch tile. 240 active threads: h = tid%60, bg = tid/60 (8 b each)
__global__ __launch_bounds__(256) void lstm_rec(
    const float* __restrict__ WhhF, const float* __restrict__ bhhF,
    const float* __restrict__ WhhB, const float* __restrict__ bhhB)
{
    extern __shared__ float sm[];
    float* Wsh = sm;                 // [60][240] : Wsh[j*240 + g] = Whh[g][j]
    float* hsh = sm + 60 * 240;      // [32][60]
    float* csh = hsh + 32 * 60;      // [32][60]

    const int dir = blockIdx.x & 1;
    const int b0 = (blockIdx.x >> 1) * 32;
    const float* __restrict__ Whh = dir ? WhhB : WhhF;
    const float* __restrict__ bhh = dir ? bhhB : bhhF;
    const int tid = threadIdx.x;

    for (int i = tid; i < 240 * 60; i += 256) {
        int g = i / 60, j = i - g * 60;
        Wsh[j * 240 + g] = Whh[i];
    }
    for (int i = tid; i < 32 * 60; i += 256) { hsh[i] = 0.f; csh[i] = 0.f; }

    const bool active = tid < 240;
    const int h = tid % 60;
    const int bg = tid / 60;
    float bI = 0, bF = 0, bG = 0, bO = 0;
    if (active) { bI = bhh[h]; bF = bhh[60 + h]; bG = bhh[120 + h]; bO = bhh[180 + h]; }
    __syncthreads();

    for (int s = 0; s < TT; s++) {
        const int t = dir ? (TT - 1 - s) : s;
        float hn[8], cn[8];
        if (active) {
            float aI[8], aF[8], aG[8], aO[8];
            #pragma unroll
            for (int b2 = 0; b2 < 8; b2++) { aI[b2] = 0; aF[b2] = 0; aG[b2] = 0; aO[b2] = 0; }
            #pragma unroll 6
            for (int j = 0; j < 60; j++) {
                float wi = Wsh[j * 240 + h];
                float wf = Wsh[j * 240 + 60 + h];
                float wg = Wsh[j * 240 + 120 + h];
                float wo = Wsh[j * 240 + 180 + h];
                #pragma unroll
                for (int b2 = 0; b2 < 8; b2++) {
                    float hv = hsh[(bg * 8 + b2) * 60 + j];
                    aI[b2] = fmaf(wi, hv, aI[b2]);
                    aF[b2] = fmaf(wf, hv, aF[b2]);
                    aG[b2] = fmaf(wg, hv, aG[b2]);
                    aO[b2] = fmaf(wo, hv, aO[b2]);
                }
            }
            #pragma unroll
            for (int b2 = 0; b2 < 8; b2++) {
                int bl = bg * 8 + b2;
                const float* gp = g_gi_lstm + ((size_t)t * BB + b0 + bl) * 480 + dir * 240;
                float iv = sigf(gp[h]        + aI[b2] + bI);
                float fv = sigf(gp[60 + h]   + aF[b2] + bF);
                float gv = tanhf(gp[120 + h] + aG[b2] + bG);
                float ov = sigf(gp[180 + h]  + aO[b2] + bO);
                float c  = fmaf(fv, csh[bl * 60 + h], iv * gv);
                cn[b2] = c;
                hn[b2] = ov * tanhf(c);
            }
        }
        __syncthreads();
        if (active) {
            #pragma unroll
            for (int b2 = 0; b2 < 8; b2++) {
                int bl = bg * 8 + b2;
                hsh[bl * 60 + h] = hn[b2];
                csh[bl * 60 + h] = cn[b2];
                g_h_lstm[((size_t)t * BB + b0 + bl) * 120 + dir * 60 + h] = hn[b2];
            }
        }
        __syncthreads();
    }
}

// ---------------- GRU recurrence ----------------
__global__ __launch_bounds__(256) void gru_rec(
    const float* __restrict__ WhhF, const float* __restrict__ bhhF,
    const float* __restrict__ WhhB, const float* __restrict__ bhhB)
{
    extern __shared__ float sm[];
    float* Wsh = sm;                 // [60][180]
    float* hsh = sm + 60 * 180;      // [32][60]

    const int dir = blockIdx.x & 1;
    const int b0 = (blockIdx.x >> 1) * 32;
    const float* __restrict__ Whh = dir ? WhhB : WhhF;
    const float* __restrict__ bhh = dir ? bhhB : bhhF;
    const int tid = threadIdx.x;

    for (int i = tid; i < 180 * 60; i += 256) {
        int g = i / 60, j = i - g * 60;
        Wsh[j * 180 + g] = Whh[i];
    }
    for (int i = tid; i < 32 * 60; i += 256) hsh[i] = 0.f;

    const bool active = tid < 240;
    const int h = tid % 60;
    const int bg = tid / 60;
    float bR = 0, bZ = 0, bN = 0;
    if (active) { bR = bhh[h]; bZ = bhh[60 + h]; bN = bhh[120 + h]; }
    __syncthreads();

    for (int s = 0; s < TT; s++) {
        const int t = dir ? (TT - 1 - s) : s;
        float hn[8];
        if (active) {
            float aR[8], aZ[8], aN[8];
            #pragma unroll
            for (int b2 = 0; b2 < 8; b2++) { aR[b2] = 0; aZ[b2] = 0; aN[b2] = 0; }
            #pragma unroll 6
            for (int j = 0; j < 60; j++) {
                float wr = Wsh[j * 180 + h];
                float wz = Wsh[j * 180 + 60 + h];
                float wn = Wsh[j * 180 + 120 + h];
                #pragma unroll
                for (int b2 = 0; b2 < 8; b2++) {
                    float hv = hsh[(bg * 8 + b2) * 60 + j];
                    aR[b2] = fmaf(wr, hv, aR[b2]);
                    aZ[b2] = fmaf(wz, hv, aZ[b2]);
                    aN[b2] = fmaf(wn, hv, aN[b2]);
                }
            }
            #pragma unroll
            for (int b2 = 0; b2 < 8; b2++) {
                int bl = bg * 8 + b2;
                const float* gp = g_gi_gru + ((size_t)t * BB + b0 + bl) * 360 + dir * 180;
                float r = sigf(gp[h]      + aR[b2] + bR);
                float z = sigf(gp[60 + h] + aZ[b2] + bZ);
                float n = tanhf(gp[120 + h] + r * (aN[b2] + bN));
                float hold = hsh[bl * 60 + h];
                hn[b2] = (1.f - z) * n + z * hold;
            }
        }
        __syncthreads();
        if (active) {
            #pragma unroll
            for (int b2 = 0; b2 < 8; b2++) {
                int bl = bg * 8 + b2;
                int bgl = b0 + bl;
                hsh[bl * 60 + h] = hn[b2];
                g_h_gru[(size_t)bgl * TT * 120 + t * 120 + dir * 60 + h] = hn[b2];
                if (s == TT - 1) {
                    if (dir) g_ghb[bgl * 60 + h] = hn[b2];
                    else     g_ghf[bgl * 60 + h] = hn[b2];
                }
            }
        }
        __syncthreads();
    }
}

// ---------------- final: attention + pools + linear + BN + out ----------------
__global__ __launch_bounds__(128) void final_kernel(
    const float* __restrict__ fin,
    const float* __restrict__ attn_w, const float* __restrict__ attn_b,
    const float* __restrict__ linW, const float* __restrict__ linb,
    const float* __restrict__ gamma, const float* __restrict__ beta,
    const float* __restrict__ mean, const float* __restrict__ var,
    const float* __restrict__ outW, const float* __restrict__ outb,
    float* __restrict__ out)
{
    __shared__ float hs[TT * 120];     // 33.6 KB
    __shared__ float att[TT];
    __shared__ float conc[484];
    __shared__ float o16[16];
    __shared__ float asum_s;

    const int b = blockIdx.x;
    const int tid = threadIdx.x;
    const float* hp = g_h_gru + (size_t)b * TT * 120;

    for (int i = tid; i < TT * 120; i += 128) hs[i] = hp[i];
    __syncthreads();

    const int warp = tid >> 5, lane = tid & 31;
    for (int t = warp; t < TT; t += 4) {
        float s = 0.f;
        for (int k = lane; k < 120; k += 32) s = fmaf(hs[t * 120 + k], attn_w[k], s);
        #pragma unroll
        for (int o = 16; o > 0; o >>= 1) s += __shfl_xor_sync(0xffffffffu, s, o);
        if (lane == 0) att[t] = expf(tanhf(s) + attn_b[t]);
    }
    __syncthreads();
    if (tid == 0) {
        float s = 0.f;
        for (int t = 0; t < TT; t++) s += att[t];
        asum_s = s + 1e-10f;
    }
    __syncthreads();
    const float inva = 1.f / asum_s;

    if (tid < 120) {
        const int fidx = tid;
        float hat = 0.f, avg = 0.f, mx = -INFINITY;
        for (int t = 0; t < TT; t++) {
            float v = hs[t * 120 + fidx];
            hat = fmaf(v, att[t], hat);
            avg += v;
            mx = fmaxf(mx, v);
        }
        conc[120 + fidx] = hat * inva;
        conc[240 + fidx] = avg * (1.f / (float)TT);
        conc[360 + fidx] = mx;
        // hh_gru = stack([ghf, ghb], 0).reshape(-1, 120) interleaving
        float hhv;
        int sub = (fidx >= 60) ? 1 : 0;
        int col = fidx - sub * 60;
        if (b < BB / 2) hhv = g_ghf[(2 * b + sub) * 60 + col];
        else            hhv = g_ghb[(2 * (b - BB / 2) + sub) * 60 + col];
        conc[fidx] = hhv;
    }
    if (tid == 0) conc[480] = fin[b];
    __syncthreads();

    if (tid < 16) {
        float s = linb[tid];
        const float* w = linW + tid * 481;
        for (int k = 0; k < 481; k++) s = fmaf(w[k], conc[k], s);
        s = fmaxf(s, 0.f);
        s = (s - mean[tid]) * rsqrtf(var[tid] + 1e-5f) * gamma[tid] + beta[tid];
        o16[tid] = s;
    }
    __syncthreads();
    if (tid == 0) {
        float s = outb[0];
        #pragma unroll
        for (int k = 0; k < 16; k++) s = fmaf(outW[k], o16[k], s);
        out[b] = s;
    }
}

// ---------------- launch ----------------
extern "C" void kernel_launch(void* const* d_in, const int* in_sizes, int n_in,
                              void* d_out, int out_size)
{
    const int*   tokens = (const int*)  d_in[0];
    const float* fin    = (const float*)d_in[1];
    const float* emb    = (const float*)d_in[2];
    const float* lWihF  = (const float*)d_in[3];
    const float* lWhhF  = (const float*)d_in[4];
    const float* lbihF  = (const float*)d_in[5];
    const float* lbhhF  = (const float*)d_in[6];
    const float* lWihB  = (const float*)d_in[7];
    const float* lWhhB  = (const float*)d_in[8];
    const float* lbihB  = (const float*)d_in[9];
    const float* lbhhB  = (const float*)d_in[10];
    const float* gWihF  = (const float*)d_in[11];
    const float* gWhhF  = (const float*)d_in[12];
    const float* gbihF  = (const float*)d_in[13];
    const float* gbhhF  = (const float*)d_in[14];
    const float* gWihB  = (const float*)d_in[15];
    const float* gWhhB  = (const float*)d_in[16];
    const float* gbihB  = (const float*)d_in[17];
    const float* gbhhB  = (const float*)d_in[18];
    const float* attnw  = (const float*)d_in[19];
    const float* attnb  = (const float*)d_in[20];
    const float* linW   = (const float*)d_in[21];
    const float* linb   = (const float*)d_in[22];
    const float* gamma  = (const float*)d_in[23];
    const float* beta   = (const float*)d_in[24];
    const float* mean   = (const float*)d_in[25];
    const float* var    = (const float*)d_in[26];
    const float* outW   = (const float*)d_in[27];
    const float* outb   = (const float*)d_in[28];
    float* out = (float*)d_out;

    const int lstm_smem = (60 * 240 + 2 * 32 * 60) * 4;   // 72960 B
    const int gru_smem  = (60 * 180 + 32 * 60) * 4;       // 50880 B
    cudaFuncSetAttribute(lstm_rec, cudaFuncAttributeMaxDynamicSharedMemorySize, lstm_smem);
    cudaFuncSetAttribute(gru_rec,  cudaFuncAttributeMaxDynamicSharedMemorySize, gru_smem);

    dim3 blk(256);
    gemm_k<0><<<dim3(RR / 128, 5), blk>>>(emb, tokens, lWihF, lWihB, lbihF, lbihB);
    lstm_rec<<<2 * (BB / 32), blk, lstm_smem>>>(lWhhF, lbhhF, lWhhB, lbhhB);
    gemm_k<1><<<dim3(RR / 128, 4), blk>>>(nullptr, nullptr, gWihF, gWihB, gbihF, gbihB);
    gru_rec<<<2 * (BB / 32), blk, gru_smem>>>(gWhhF, gbhhF, gWhhB, gbhhB);
    final_kernel<<<BB, 128>>>(fin, attnw, attnb, linW, linb,
                              gamma, beta, mean, var, outW, outb, out);
}

// round 2
// speedup vs baseline: 1.4599x; 1.4599x over previous
#include <cuda_runtime.h>
#include <math.h>

#define BB 4096
#define TT 70
#define EE 300
#define HH 60
#define VV 120000
#define RR (BB*TT)   // 286720 rows

// ---------------- scratch (static device memory; no allocations) ----------------
__device__ float g_proj  [(size_t)VV*480];  // P[v][480] = emb[v] @ [WihF;WihB]^T + bih
__device__ float g_h_lstm[(size_t)RR*120];  // [T][B][120]  (fwd 0..59, bwd 60..119)
__device__ float g_gi_gru[(size_t)RR*360];  // [T][B][360]  (fwd 0..179, bwd 180..359)
__device__ float g_h_gru [(size_t)RR*120];  // [B][T][120]
__device__ float g_ghf   [BB*HH];
__device__ float g_ghb   [BB*HH];

__device__ __forceinline__ float sigf(float x) { return 1.f / (1.f + __expf(-x)); }

// ---------------- GEMM: C[r][n] = sum_k A[r][k] * W[n][k] + bias[n] ----------------
// MODE 1: A = g_h_lstm (K=120), W = [gru_Wih_f; gru_Wih_b] (N=360) -> g_gi_gru
// MODE 2: A = emb (K=300, M=VV), W = [lstm_Wih_f; lstm_Wih_b] (N=480) -> g_proj
template<int MODE>
__global__ __launch_bounds__(256) void gemm_k(
    const float* __restrict__ Ain,
    const float* __restrict__ W0, const float* __restrict__ W1,
    const float* __restrict__ bias0, const float* __restrict__ bias1)
{
    constexpr int N  = (MODE == 2) ? 480 : 360;
    constexpr int K  = (MODE == 2) ? 300 : 120;
    constexpr int NS = (MODE == 2) ? 240 : 180;
    constexpr int M  = (MODE == 2) ? VV  : RR;
    constexpr int TM = 128, TN = 96, TK = 20;

    __shared__ float Ash[TK][TM + 1];
    __shared__ float Bsh[TK][TN + 1];
    __shared__ int rbase[TM];

    float* __restrict__ C = (MODE == 2) ? g_proj : g_gi_gru;
    const float* __restrict__ A = (MODE == 2) ? Ain : (const float*)g_h_lstm;

    const int m0 = blockIdx.x * TM;
    const int n0 = blockIdx.y * TN;
    const int tid = threadIdx.x;

    for (int i = tid; i < TM; i += 256) {
        int r = m0 + i;
        if (r >= M) r = M - 1;
        rbase[i] = r * K;
    }

    float acc[8][6];
    #pragma unroll
    for (int i = 0; i < 8; i++)
        #pragma unroll
        for (int j = 0; j < 6; j++) acc[i][j] = 0.f;

    const int tx = tid & 15;   // 16 cols of threads -> 6 n each
    const int ty = tid >> 4;   // 16 rows of threads -> 8 m each
    __syncthreads();

    for (int k0 = 0; k0 < K; k0 += TK) {
        #pragma unroll
        for (int it = 0; it < (TM * TK) / 256; it++) {
            int i = tid + it * 256;
            int m = i / TK, kk = i - m * TK;
            Ash[kk][m] = A[rbase[m] + k0 + kk];
        }
        for (int i = tid; i < TK * TN; i += 256) {
            int n = i / TK, kk = i - n * TK;
            int ng = n0 + n;
            float v = 0.f;
            if (ng < N)
                v = (ng < NS) ? W0[ng * K + k0 + kk] : W1[(ng - NS) * K + k0 + kk];
            Bsh[kk][n] = v;
        }
        __syncthreads();
        #pragma unroll
        for (int kk = 0; kk < TK; kk++) {
            float a[8], bv[6];
            #pragma unroll
            for (int i = 0; i < 8; i++) a[i] = Ash[kk][ty * 8 + i];
            #pragma unroll
            for (int j = 0; j < 6; j++) bv[j] = Bsh[kk][tx * 6 + j];
            #pragma unroll
            for (int i = 0; i < 8; i++)
                #pragma unroll
                for (int j = 0; j < 6; j++)
                    acc[i][j] = fmaf(a[i], bv[j], acc[i][j]);
        }
        __syncthreads();
    }

    #pragma unroll
    for (int j = 0; j < 6; j++) {
        int ng = n0 + tx * 6 + j;
        if (ng < N) {
            float bv = (ng < NS) ? bias0[ng] : bias1[ng - NS];
            #pragma unroll
            for (int i = 0; i < 8; i++) {
                int mg = m0 + ty * 8 + i;
                if (mg < M)
                    C[(size_t)mg * N + ng] = acc[i][j] + bv;
            }
        }
    }
}

// ---------------- LSTM recurrence (both directions; 32-batch tiles) ----------------
// Input projection read directly from g_proj via token gather (bih already folded in).
__global__ __launch_bounds__(256) void lstm_rec(
    const int* __restrict__ tokens,
    const float* __restrict__ WhhF, const float* __restrict__ bhhF,
    const float* __restrict__ WhhB, const float* __restrict__ bhhB)
{
    extern __shared__ float sm[];
    float* Wsh = sm;                 // [60][240] : Wsh[j*240 + g] = Whh[g][j]
    float* hsh = sm + 60 * 240;      // [32][60]
    float* csh = hsh + 32 * 60;      // [32][60]
    int*   tsh = (int*)(csh + 32 * 60); // [32][70]

    const int dir = blockIdx.x & 1;
    const int b0 = (blockIdx.x >> 1) * 32;
    const float* __restrict__ Whh = dir ? WhhB : WhhF;
    const float* __restrict__ bhh = dir ? bhhB : bhhF;
    const int tid = threadIdx.x;

    for (int i = tid; i < 240 * 60; i += 256) {
        int g = i / 60, j = i - g * 60;
        Wsh[j * 240 + g] = Whh[i];
    }
    for (int i = tid; i < 32 * 60; i += 256) { hsh[i] = 0.f; csh[i] = 0.f; }
    for (int i = tid; i < 32 * TT; i += 256) tsh[i] = tokens[b0 * TT + i];

    const bool active = tid < 240;
    const int h = tid % 60;
    const int bg = tid / 60;
    float bI = 0, bF = 0, bG = 0, bO = 0;
    if (active) { bI = bhh[h]; bF = bhh[60 + h]; bG = bhh[120 + h]; bO = bhh[180 + h]; }
    __syncthreads();

    for (int s = 0; s < TT; s++) {
        const int t = dir ? (TT - 1 - s) : s;
        float hn[8], cn[8];
        if (active) {
            float aI[8], aF[8], aG[8], aO[8];
            #pragma unroll
            for (int b2 = 0; b2 < 8; b2++) { aI[b2] = 0; aF[b2] = 0; aG[b2] = 0; aO[b2] = 0; }
            #pragma unroll 6
            for (int j = 0; j < 60; j++) {
                float wi = Wsh[j * 240 + h];
                float wf = Wsh[j * 240 + 60 + h];
                float wg = Wsh[j * 240 + 120 + h];
                float wo = Wsh[j * 240 + 180 + h];
                #pragma unroll
                for (int b2 = 0; b2 < 8; b2++) {
                    float hv = hsh[(bg * 8 + b2) * 60 + j];
                    aI[b2] = fmaf(wi, hv, aI[b2]);
                    aF[b2] = fmaf(wf, hv, aF[b2]);
                    aG[b2] = fmaf(wg, hv, aG[b2]);
                    aO[b2] = fmaf(wo, hv, aO[b2]);
                }
            }
            #pragma unroll
            for (int b2 = 0; b2 < 8; b2++) {
                int bl = bg * 8 + b2;
                int tok = tsh[bl * TT + t];
                const float* gp = g_proj + (size_t)tok * 480 + dir * 240;
                float iv = sigf(gp[h]        + aI[b2] + bI);
                float fv = sigf(gp[60 + h]   + aF[b2] + bF);
                float gv = tanhf(gp[120 + h] + aG[b2] + bG);
                float ov = sigf(gp[180 + h]  + aO[b2] + bO);
                float c  = fmaf(fv, csh[bl * 60 + h], iv * gv);
                cn[b2] = c;
                hn[b2] = ov * tanhf(c);
            }
        }
        __syncthreads();
        if (active) {
            #pragma unroll
            for (int b2 = 0; b2 < 8; b2++) {
                int bl = bg * 8 + b2;
                hsh[bl * 60 + h] = hn[b2];
                csh[bl * 60 + h] = cn[b2];
                g_h_lstm[((size_t)t * BB + b0 + bl) * 120 + dir * 60 + h] = hn[b2];
            }
        }
        __syncthreads();
    }
}

// ---------------- GRU recurrence ----------------
__global__ __launch_bounds__(256) void gru_rec(
    const float* __restrict__ WhhF, const float* __restrict__ bhhF,
    const float* __restrict__ WhhB, const float* __restrict__ bhhB)
{
    extern __shared__ float sm[];
    float* Wsh = sm;                 // [60][180]
    float* hsh = sm + 60 * 180;      // [32][60]

    const int dir = blockIdx.x & 1;
    const int b0 = (blockIdx.x >> 1) * 32;
    const float* __restrict__ Whh = dir ? WhhB : WhhF;
    const float* __restrict__ bhh = dir ? bhhB : bhhF;
    const int tid = threadIdx.x;

    for (int i = tid; i < 180 * 60; i += 256) {
        int g = i / 60, j = i - g * 60;
        Wsh[j * 180 + g] = Whh[i];
    }
    for (int i = tid; i < 32 * 60; i += 256) hsh[i] = 0.f;

    const bool active = tid < 240;
    const int h = tid % 60;
    const int bg = tid / 60;
    float bR = 0, bZ = 0, bN = 0;
    if (active) { bR = bhh[h]; bZ = bhh[60 + h]; bN = bhh[120 + h]; }
    __syncthreads();

    for (int s = 0; s < TT; s++) {
        const int t = dir ? (TT - 1 - s) : s;
        float hn[8];
        if (active) {
            float aR[8], aZ[8], aN[8];
            #pragma unroll
            for (int b2 = 0; b2 < 8; b2++) { aR[b2] = 0; aZ[b2] = 0; aN[b2] = 0; }
            #pragma unroll 6
            for (int j = 0; j < 60; j++) {
                float wr = Wsh[j * 180 + h];
                float wz = Wsh[j * 180 + 60 + h];
                float wn = Wsh[j * 180 + 120 + h];
                #pragma unroll
                for (int b2 = 0; b2 < 8; b2++) {
                    float hv = hsh[(bg * 8 + b2) * 60 + j];
                    aR[b2] = fmaf(wr, hv, aR[b2]);
                    aZ[b2] = fmaf(wz, hv, aZ[b2]);
                    aN[b2] = fmaf(wn, hv, aN[b2]);
                }
            }
            #pragma unroll
            for (int b2 = 0; b2 < 8; b2++) {
                int bl = bg * 8 + b2;
                const float* gp = g_gi_gru + ((size_t)t * BB + b0 + bl) * 360 + dir * 180;
                float r = sigf(gp[h]      + aR[b2] + bR);
                float z = sigf(gp[60 + h] + aZ[b2] + bZ);
                float n = tanhf(gp[120 + h] + r * (aN[b2] + bN));
                float hold = hsh[bl * 60 + h];
                hn[b2] = (1.f - z) * n + z * hold;
            }
        }
        __syncthreads();
        if (active) {
            #pragma unroll
            for (int b2 = 0; b2 < 8; b2++) {
                int bl = bg * 8 + b2;
                int bgl = b0 + bl;
                hsh[bl * 60 + h] = hn[b2];
                g_h_gru[(size_t)bgl * TT * 120 + t * 120 + dir * 60 + h] = hn[b2];
                if (s == TT - 1) {
                    if (dir) g_ghb[bgl * 60 + h] = hn[b2];
                    else     g_ghf[bgl * 60 + h] = hn[b2];
                }
            }
        }
        __syncthreads();
    }
}

// ---------------- final: attention + pools + linear + BN + out ----------------
__global__ __launch_bounds__(128) void final_kernel(
    const float* __restrict__ fin,
    const float* __restrict__ attn_w, const float* __restrict__ attn_b,
    const float* __restrict__ linW, const float* __restrict__ linb,
    const float* __restrict__ gamma, const float* __restrict__ beta,
    const float* __restrict__ mean, const float* __restrict__ var,
    const float* __restrict__ outW, const float* __restrict__ outb,
    float* __restrict__ out)
{
    __shared__ float hs[TT * 120];     // 33.6 KB
    __shared__ float att[TT];
    __shared__ float conc[484];
    __shared__ float o16[16];
    __shared__ float asum_s;

    const int b = blockIdx.x;
    const int tid = threadIdx.x;
    const float* hp = g_h_gru + (size_t)b * TT * 120;

    for (int i = tid; i < TT * 120; i += 128) hs[i] = hp[i];
    __syncthreads();

    const int warp = tid >> 5, lane = tid & 31;
    for (int t = warp; t < TT; t += 4) {
        float s = 0.f;
        for (int k = lane; k < 120; k += 32) s = fmaf(hs[t * 120 + k], attn_w[k], s);
        #pragma unroll
        for (int o = 16; o > 0; o >>= 1) s += __shfl_xor_sync(0xffffffffu, s, o);
        if (lane == 0) att[t] = expf(tanhf(s) + attn_b[t]);
    }
    __syncthreads();
    if (tid == 0) {
        float s = 0.f;
        for (int t = 0; t < TT; t++) s += att[t];
        asum_s = s + 1e-10f;
    }
    __syncthreads();
    const float inva = 1.f / asum_s;

    if (tid < 120) {
        const int fidx = tid;
        float hat = 0.f, avg = 0.f, mx = -INFINITY;
        for (int t = 0; t < TT; t++) {
            float v = hs[t * 120 + fidx];
            hat = fmaf(v, att[t], hat);
            avg += v;
            mx = fmaxf(mx, v);
        }
        conc[120 + fidx] = hat * inva;
        conc[240 + fidx] = avg * (1.f / (float)TT);
        conc[360 + fidx] = mx;
        float hhv;
        int sub = (fidx >= 60) ? 1 : 0;
        int col = fidx - sub * 60;
        if (b < BB / 2) hhv = g_ghf[(2 * b + sub) * 60 + col];
        else            hhv = g_ghb[(2 * (b - BB / 2) + sub) * 60 + col];
        conc[fidx] = hhv;
    }
    if (tid == 0) conc[480] = fin[b];
    __syncthreads();

    if (tid < 16) {
        float s = linb[tid];
        const float* w = linW + tid * 481;
        for (int k = 0; k < 481; k++) s = fmaf(w[k], conc[k], s);
        s = fmaxf(s, 0.f);
        s = (s - mean[tid]) * rsqrtf(var[tid] + 1e-5f) * gamma[tid] + beta[tid];
        o16[tid] = s;
    }
    __syncthreads();
    if (tid == 0) {
        float s = outb[0];
        #pragma unroll
        for (int k = 0; k < 16; k++) s = fmaf(outW[k], o16[k], s);
        out[b] = s;
    }
}

// ---------------- launch ----------------
extern "C" void kernel_launch(void* const* d_in, const int* in_sizes, int n_in,
                              void* d_out, int out_size)
{
    const int*   tokens = (const int*)  d_in[0];
    const float* fin    = (const float*)d_in[1];
    const float* emb    = (const float*)d_in[2];
    const float* lWihF  = (const float*)d_in[3];
    const float* lWhhF  = (const float*)d_in[4];
    const float* lbihF  = (const float*)d_in[5];
    const float* lbhhF  = (const float*)d_in[6];
    const float* lWihB  = (const float*)d_in[7];
    const float* lWhhB  = (const float*)d_in[8];
    const float* lbihB  = (const float*)d_in[9];
    const float* lbhhB  = (const float*)d_in[10];
    const float* gWihF  = (const float*)d_in[11];
    const float* gWhhF  = (const float*)d_in[12];
    const float* gbihF  = (const float*)d_in[13];
    const float* gbhhF  = (const float*)d_in[14];
    const float* gWihB  = (const float*)d_in[15];
    const float* gWhhB  = (const float*)d_in[16];
    const float* gbihB  = (const float*)d_in[17];
    const float* gbhhB  = (const float*)d_in[18];
    const float* attnw  = (const float*)d_in[19];
    const float* attnb  = (const float*)d_in[20];
    const float* linW   = (const float*)d_in[21];
    const float* linb   = (const float*)d_in[22];
    const float* gamma  = (const float*)d_in[23];
    const float* beta   = (const float*)d_in[24];
    const float* mean   = (const float*)d_in[25];
    const float* var    = (const float*)d_in[26];
    const float* outW   = (const float*)d_in[27];
    const float* outb   = (const float*)d_in[28];
    float* out = (float*)d_out;

    const int lstm_smem = (60 * 240 + 2 * 32 * 60) * 4 + 32 * TT * 4;  // 81920 B
    const int gru_smem  = (60 * 180 + 32 * 60) * 4;                    // 50880 B
    cudaFuncSetAttribute(lstm_rec, cudaFuncAttributeMaxDynamicSharedMemorySize, lstm_smem);
    cudaFuncSetAttribute(gru_rec,  cudaFuncAttributeMaxDynamicSharedMemorySize, gru_smem);

    dim3 blk(256);
    // 1) vocab projection table: P[v] = emb[v] @ [WihF;WihB]^T + bih   (34.6 GFLOP)
    gemm_k<2><<<dim3((VV + 127) / 128, 5), blk>>>(emb, lWihF, lWihB, lbihF, lbihB);
    // 2) LSTM recurrence with direct P-table gather
    lstm_rec<<<2 * (BB / 32), blk, lstm_smem>>>(tokens, lWhhF, lbhhF, lWhhB, lbhhB);
    // 3) GRU input projection GEMM
    gemm_k<1><<<dim3(RR / 128, 4), blk>>>(nullptr, gWihF, gWihB, gbihF, gbihB);
    // 4) GRU recurrence
    gru_rec<<<2 * (BB / 32), blk, gru_smem>>>(gWhhF, gbhhF, gWhhB, gbhhB);
    // 5) epilogue
    final_kernel<<<BB, 128>>>(fin, attnw, attnb, linW, linb,
                              gamma, beta, mean, var, outW, outb, out);
}

// round 3
// speedup vs baseline: 2.1559x; 1.4768x over previous
#include <cuda_runtime.h>
#include <math.h>

#define BB 4096
#define TT 70
#define EE 300
#define HH 60
#define VV 120000
#define RR (BB*TT)   // 286720 rows

// ---------------- scratch (static device memory; no allocations) ----------------
__device__ float g_proj  [(size_t)VV*480];  // P[v][480] = emb[v] @ [WihF;WihB]^T + bih
__device__ float g_h_lstm[(size_t)RR*120];  // [T][B][120]  (fwd 0..59, bwd 60..119)
__device__ float g_gi_gru[(size_t)RR*360];  // [T][B][360]  (fwd 0..179, bwd 180..359)
__device__ float g_h_gru [(size_t)RR*120];  // [B][T][120]
__device__ float g_ghf   [BB*HH];
__device__ float g_ghb   [BB*HH];

__device__ __forceinline__ float sigf(float x) { return 1.f / (1.f + __expf(-x)); }

// ---------------- GEMM: C[r][n] = sum_k A[r][k] * W[n][k] + bias[n] ----------------
// 128x128x20 tile, 256 threads, 8x8 per thread (4+4 split for conflict-free LDS.128)
// MODE 1: A = g_h_lstm (K=120, M=RR), W = [gru_Wih_f; gru_Wih_b] (N=360) -> g_gi_gru
// MODE 2: A = emb (K=300, M=VV),      W = [lstm_Wih_f; lstm_Wih_b] (N=480) -> g_proj
template<int MODE>
__global__ __launch_bounds__(256) void gemm_k(
    const float* __restrict__ Ain,
    const float* __restrict__ W0, const float* __restrict__ W1,
    const float* __restrict__ bias0, const float* __restrict__ bias1)
{
    constexpr int N  = (MODE == 2) ? 480 : 360;
    constexpr int K  = (MODE == 2) ? 300 : 120;
    constexpr int NS = (MODE == 2) ? 240 : 180;
    constexpr int M  = (MODE == 2) ? VV  : RR;
    constexpr int TM = 128, TN = 128, TK = 20;

    __shared__ float Ash[TK][TM];
    __shared__ float Bsh[TK][TN];
    __shared__ int rbase[TM];

    float* __restrict__ C = (MODE == 2) ? g_proj : g_gi_gru;
    const float* __restrict__ A = (MODE == 2) ? Ain : (const float*)g_h_lstm;

    const int m0 = blockIdx.x * TM;
    const int n0 = blockIdx.y * TN;
    const int tid = threadIdx.x;
    const int tx = tid & 15;
    const int ty = tid >> 4;

    for (int i = tid; i < TM; i += 256) {
        int r = m0 + i;
        if (r >= M) r = M - 1;
        rbase[i] = r * K;
    }
    __syncthreads();

    float acc[8][8];
    #pragma unroll
    for (int i = 0; i < 8; i++)
        #pragma unroll
        for (int j = 0; j < 8; j++) acc[i][j] = 0.f;

    for (int k0 = 0; k0 < K; k0 += TK) {
        // A tile: 128 rows x 5 float4 = 640 vec loads
        for (int i = tid; i < TM * (TK / 4); i += 256) {
            int row = i / (TK / 4), kq = i % (TK / 4);
            float4 v = *(const float4*)(A + rbase[row] + k0 + kq * 4);
            Ash[kq * 4 + 0][row] = v.x;
            Ash[kq * 4 + 1][row] = v.y;
            Ash[kq * 4 + 2][row] = v.z;
            Ash[kq * 4 + 3][row] = v.w;
        }
        // B tile
        for (int i = tid; i < TN * (TK / 4); i += 256) {
            int nrow = i / (TK / 4), kq = i % (TK / 4);
            int ng = n0 + nrow;
            float4 v = make_float4(0.f, 0.f, 0.f, 0.f);
            if (ng < N) {
                const float* wp = (ng < NS) ? (W0 + (size_t)ng * K)
                                            : (W1 + (size_t)(ng - NS) * K);
                v = *(const float4*)(wp + k0 + kq * 4);
            }
            Bsh[kq * 4 + 0][nrow] = v.x;
            Bsh[kq * 4 + 1][nrow] = v.y;
            Bsh[kq * 4 + 2][nrow] = v.z;
            Bsh[kq * 4 + 3][nrow] = v.w;
        }
        __syncthreads();
        #pragma unroll
        for (int kk = 0; kk < TK; kk++) {
            float4 a0 = *(const float4*)&Ash[kk][ty * 4];
            float4 a1 = *(const float4*)&Ash[kk][64 + ty * 4];
            float4 b0 = *(const float4*)&Bsh[kk][tx * 4];
            float4 b1 = *(const float4*)&Bsh[kk][64 + tx * 4];
            float av[8] = {a0.x, a0.y, a0.z, a0.w, a1.x, a1.y, a1.z, a1.w};
            float bv[8] = {b0.x, b0.y, b0.z, b0.w, b1.x, b1.y, b1.z, b1.w};
            #pragma unroll
            for (int i = 0; i < 8; i++)
                #pragma unroll
                for (int j = 0; j < 8; j++)
                    acc[i][j] = fmaf(av[i], bv[j], acc[i][j]);
        }
        __syncthreads();
    }

    // epilogue: bias + store (float4 when possible)
    float bb[8];
    #pragma unroll
    for (int j = 0; j < 8; j++) {
        int ng = n0 + ((j < 4) ? tx * 4 + j : 64 + tx * 4 + j - 4);
        bb[j] = 0.f;
        if (ng < N) bb[j] = (ng < NS) ? bias0[ng] : bias1[ng - NS];
    }
    #pragma unroll
    for (int i = 0; i < 8; i++) {
        int mg = m0 + ((i < 4) ? ty * 4 + i : 64 + ty * 4 + i - 4);
        if (mg >= M) continue;
        float* crow = C + (size_t)mg * N;
        #pragma unroll
        for (int half = 0; half < 2; half++) {
            int nbase = n0 + half * 64 + tx * 4;
            if (nbase + 3 < N) {
                float4 v;
                v.x = acc[i][half * 4 + 0] + bb[half * 4 + 0];
                v.y = acc[i][half * 4 + 1] + bb[half * 4 + 1];
                v.z = acc[i][half * 4 + 2] + bb[half * 4 + 2];
                v.w = acc[i][half * 4 + 3] + bb[half * 4 + 3];
                *(float4*)(crow + nbase) = v;
            } else {
                #pragma unroll
                for (int j = 0; j < 4; j++)
                    if (nbase + j < N)
                        crow[nbase + j] = acc[i][half * 4 + j] + bb[half * 4 + j];
            }
        }
    }
}

// ---------------- LSTM recurrence: 64-batch tiles, 512 threads, packed-gate smem ----------------
__global__ __launch_bounds__(512) void lstm_rec(
    const int* __restrict__ tokens,
    const float* __restrict__ WhhF, const float* __restrict__ bhhF,
    const float* __restrict__ WhhB, const float* __restrict__ bhhB)
{
    extern __shared__ float sm[];
    float* Wsh = sm;                   // [60][60][4]: Wsh[j*240 + h*4 + gate]
    float* hsh = Wsh + 60 * 240;       // [60][68]:    hsh[j*68 + bl]
    float* csh = hsh + 60 * 68;        // [64][60]:    csh[bl*60 + h]
    int*   tsh = (int*)(csh + 64 * 60);// [64][70]

    const int dir = blockIdx.x & 1;
    const int b0 = (blockIdx.x >> 1) * 64;
    const float* __restrict__ Whh = dir ? WhhB : WhhF;
    const float* __restrict__ bhh = dir ? bhhB : bhhF;
    const int tid = threadIdx.x;

    // Whh[gate*60+h][j] -> Wsh[j*240 + h*4 + gate]
    for (int i = tid; i < 240 * 60; i += 512) {
        int row = i / 60, j = i - row * 60;   // row = gate*60+h
        int gate = row / 60, h = row - gate * 60;
        Wsh[j * 240 + h * 4 + gate] = Whh[i];
    }
    for (int i = tid; i < 60 * 68; i += 512) hsh[i] = 0.f;
    for (int i = tid; i < 64 * 60; i += 512) csh[i] = 0.f;
    for (int i = tid; i < 64 * TT; i += 512) tsh[i] = tokens[b0 * TT + i];

    const bool active = tid < 480;
    const int h = tid % 60;
    const int bg = tid / 60;     // 0..7 -> 8 batches each
    float bI = 0, bF = 0, bG = 0, bO = 0;
    if (active) { bI = bhh[h]; bF = bhh[60 + h]; bG = bhh[120 + h]; bO = bhh[180 + h]; }
    __syncthreads();

    for (int s = 0; s < TT; s++) {
        const int t = dir ? (TT - 1 - s) : s;
        float hn[8], cn[8];
        if (active) {
            float aI[8], aF[8], aG[8], aO[8];
            #pragma unroll
            for (int b2 = 0; b2 < 8; b2++) { aI[b2] = 0; aF[b2] = 0; aG[b2] = 0; aO[b2] = 0; }
            #pragma unroll 10
            for (int j = 0; j < 60; j++) {
                float4 w = *(const float4*)&Wsh[j * 240 + h * 4];
                float4 h0 = *(const float4*)&hsh[j * 68 + bg * 8];
                float4 h1 = *(const float4*)&hsh[j * 68 + bg * 8 + 4];
                float hv[8] = {h0.x, h0.y, h0.z, h0.w, h1.x, h1.y, h1.z, h1.w};
                #pragma unroll
                for (int b2 = 0; b2 < 8; b2++) {
                    aI[b2] = fmaf(w.x, hv[b2], aI[b2]);
                    aF[b2] = fmaf(w.y, hv[b2], aF[b2]);
                    aG[b2] = fmaf(w.z, hv[b2], aG[b2]);
                    aO[b2] = fmaf(w.w, hv[b2], aO[b2]);
                }
            }
            #pragma unroll
            for (int b2 = 0; b2 < 8; b2++) {
                int bl = bg * 8 + b2;
                int tok = tsh[bl * TT + t];
                const float* gp = g_proj + (size_t)tok * 480 + dir * 240;
                float iv = sigf(gp[h]        + aI[b2] + bI);
                float fv = sigf(gp[60 + h]   + aF[b2] + bF);
                float gv = tanhf(gp[120 + h] + aG[b2] + bG);
                float ov = sigf(gp[180 + h]  + aO[b2] + bO);
                float c  = fmaf(fv, csh[bl * 60 + h], iv * gv);
                cn[b2] = c;
                hn[b2] = ov * tanhf(c);
            }
        }
        __syncthreads();
        if (active) {
            #pragma unroll
            for (int b2 = 0; b2 < 8; b2++) {
                int bl = bg * 8 + b2;
                hsh[h * 68 + bl] = hn[b2];
                csh[bl * 60 + h] = cn[b2];
                g_h_lstm[((size_t)t * BB + b0 + bl) * 120 + dir * 60 + h] = hn[b2];
            }
        }
        __syncthreads();
    }
}

// ---------------- GRU recurrence: 64-batch tiles, 512 threads ----------------
__global__ __launch_bounds__(512) void gru_rec(
    const float* __restrict__ WhhF, const float* __restrict__ bhhF,
    const float* __restrict__ WhhB, const float* __restrict__ bhhB)
{
    extern __shared__ float sm[];
    float* Wsh = sm;                   // [60][60][4] (gate 3 = pad, unread)
    float* hsh = Wsh + 60 * 240;       // [60][68]

    const int dir = blockIdx.x & 1;
    const int b0 = (blockIdx.x >> 1) * 64;
    const float* __restrict__ Whh = dir ? WhhB : WhhF;
    const float* __restrict__ bhh = dir ? bhhB : bhhF;
    const int tid = threadIdx.x;

    for (int i = tid; i < 180 * 60; i += 512) {
        int row = i / 60, j = i - row * 60;   // row = gate*60+h
        int gate = row / 60, h = row - gate * 60;
        Wsh[j * 240 + h * 4 + gate] = Whh[i];
    }
    for (int i = tid; i < 60 * 68; i += 512) hsh[i] = 0.f;

    const bool active = tid < 480;
    const int h = tid % 60;
    const int bg = tid / 60;
    float bR = 0, bZ = 0, bN = 0;
    if (active) { bR = bhh[h]; bZ = bhh[60 + h]; bN = bhh[120 + h]; }
    __syncthreads();

    for (int s = 0; s < TT; s++) {
        const int t = dir ? (TT - 1 - s) : s;
        float hn[8];
        if (active) {
            float aR[8], aZ[8], aN[8], hold[8];
            #pragma unroll
            for (int b2 = 0; b2 < 8; b2++) { aR[b2] = 0; aZ[b2] = 0; aN[b2] = 0; }
            #pragma unroll 10
            for (int j = 0; j < 60; j++) {
                float4 w = *(const float4*)&Wsh[j * 240 + h * 4];
                float4 h0 = *(const float4*)&hsh[j * 68 + bg * 8];
                float4 h1 = *(const float4*)&hsh[j * 68 + bg * 8 + 4];
                float hv[8] = {h0.x, h0.y, h0.z, h0.w, h1.x, h1.y, h1.z, h1.w};
                #pragma unroll
                for (int b2 = 0; b2 < 8; b2++) {
                    aR[b2] = fmaf(w.x, hv[b2], aR[b2]);
                    aZ[b2] = fmaf(w.y, hv[b2], aZ[b2]);
                    aN[b2] = fmaf(w.z, hv[b2], aN[b2]);
                }
            }
            #pragma unroll
            for (int b2 = 0; b2 < 8; b2++)
                hold[b2] = hsh[h * 68 + bg * 8 + b2];   // h_prev for this (h, bl)
            #pragma unroll
            for (int b2 = 0; b2 < 8; b2++) {
                int bl = bg * 8 + b2;
                const float* gp = g_gi_gru + ((size_t)t * BB + b0 + bl) * 360 + dir * 180;
                float r = sigf(gp[h]      + aR[b2] + bR);
                float z = sigf(gp[60 + h] + aZ[b2] + bZ);
                float n = tanhf(gp[120 + h] + r * (aN[b2] + bN));
                hn[b2] = (1.f - z) * n + z * hold[b2];
            }
        }
        __syncthreads();
        if (active) {
            #pragma unroll
            for (int b2 = 0; b2 < 8; b2++) {
                int bl = bg * 8 + b2;
                int bgl = b0 + bl;
                hsh[h * 68 + bl] = hn[b2];
                g_h_gru[(size_t)bgl * TT * 120 + t * 120 + dir * 60 + h] = hn[b2];
                if (s == TT - 1) {
                    if (dir) g_ghb[bgl * 60 + h] = hn[b2];
                    else     g_ghf[bgl * 60 + h] = hn[b2];
                }
            }
        }
        __syncthreads();
    }
}

// ---------------- final: attention + pools + linear + BN + out ----------------
__global__ __launch_bounds__(128) void final_kernel(
    const float* __restrict__ fin,
    const float* __restrict__ attn_w, const float* __restrict__ attn_b,
    const float* __restrict__ linW, const float* __restrict__ linb,
    const float* __restrict__ gamma, const float* __restrict__ beta,
    const float* __restrict__ mean, const float* __restrict__ var,
    const float* __restrict__ outW, const float* __restrict__ outb,
    float* __restrict__ out)
{
    __shared__ float hs[TT * 120];
    __shared__ float att[TT];
    __shared__ float conc[484];
    __shared__ float o16[16];
    __shared__ float asum_s;

    const int b = blockIdx.x;
    const int tid = threadIdx.x;
    const float* hp = g_h_gru + (size_t)b * TT * 120;

    for (int i = tid; i < TT * 120; i += 128) hs[i] = hp[i];
    __syncthreads();

    const int warp = tid >> 5, lane = tid & 31;
    for (int t = warp; t < TT; t += 4) {
        float s = 0.f;
        for (int k = lane; k < 120; k += 32) s = fmaf(hs[t * 120 + k], attn_w[k], s);
        #pragma unroll
        for (int o = 16; o > 0; o >>= 1) s += __shfl_xor_sync(0xffffffffu, s, o);
        if (lane == 0) att[t] = expf(tanhf(s) + attn_b[t]);
    }
    __syncthreads();
    if (tid == 0) {
        float s = 0.f;
        for (int t = 0; t < TT; t++) s += att[t];
        asum_s = s + 1e-10f;
    }
    __syncthreads();
    const float inva = 1.f / asum_s;

    if (tid < 120) {
        const int fidx = tid;
        float hat = 0.f, avg = 0.f, mx = -INFINITY;
        for (int t = 0; t < TT; t++) {
            float v = hs[t * 120 + fidx];
            hat = fmaf(v, att[t], hat);
            avg += v;
            mx = fmaxf(mx, v);
        }
        conc[120 + fidx] = hat * inva;
        conc[240 + fidx] = avg * (1.f / (float)TT);
        conc[360 + fidx] = mx;
        float hhv;
        int sub = (fidx >= 60) ? 1 : 0;
        int col = fidx - sub * 60;
        if (b < BB / 2) hhv = g_ghf[(2 * b + sub) * 60 + col];
        else            hhv = g_ghb[(2 * (b - BB / 2) + sub) * 60 + col];
        conc[fidx] = hhv;
    }
    if (tid == 0) conc[480] = fin[b];
    __syncthreads();

    if (tid < 16) {
        float s = linb[tid];
        const float* w = linW + tid * 481;
        for (int k = 0; k < 481; k++) s = fmaf(w[k], conc[k], s);
        s = fmaxf(s, 0.f);
        s = (s - mean[tid]) * rsqrtf(var[tid] + 1e-5f) * gamma[tid] + beta[tid];
        o16[tid] = s;
    }
    __syncthreads();
    if (tid == 0) {
        float s = outb[0];
        #pragma unroll
        for (int k = 0; k < 16; k++) s = fmaf(outW[k], o16[k], s);
        out[b] = s;
    }
}

// ---------------- launch ----------------
extern "C" void kernel_launch(void* const* d_in, const int* in_sizes, int n_in,
                              void* d_out, int out_size)
{
    const int*   tokens = (const int*)  d_in[0];
    const float* fin    = (const float*)d_in[1];
    const float* emb    = (const float*)d_in[2];
    const float* lWihF  = (const float*)d_in[3];
    const float* lWhhF  = (const float*)d_in[4];
    const float* lbihF  = (const float*)d_in[5];
    const float* lbhhF  = (const float*)d_in[6];
    const float* lWihB  = (const float*)d_in[7];
    const float* lWhhB  = (const float*)d_in[8];
    const float* lbihB  = (const float*)d_in[9];
    const float* lbhhB  = (const float*)d_in[10];
    const float* gWihF  = (const float*)d_in[11];
    const float* gWhhF  = (const float*)d_in[12];
    const float* gbihF  = (const float*)d_in[13];
    const float* gbhhF  = (const float*)d_in[14];
    const float* gWihB  = (const float*)d_in[15];
    const float* gWhhB  = (const float*)d_in[16];
    const float* gbihB  = (const float*)d_in[17];
    const float* gbhhB  = (const float*)d_in[18];
    const float* attnw  = (const float*)d_in[19];
    const float* attnb  = (const float*)d_in[20];
    const float* linW   = (const float*)d_in[21];
    const float* linb   = (const float*)d_in[22];
    const float* gamma  = (const float*)d_in[23];
    const float* beta   = (const float*)d_in[24];
    const float* mean   = (const float*)d_in[25];
    const float* var    = (const float*)d_in[26];
    const float* outW   = (const float*)d_in[27];
    const float* outb   = (const float*)d_in[28];
    float* out = (float*)d_out;

    const int lstm_smem = (60*240 + 60*68 + 64*60) * 4 + 64*TT*4;  // ~107 KB
    const int gru_smem  = (60*240 + 60*68) * 4;                    // ~74 KB
    cudaFuncSetAttribute(lstm_rec, cudaFuncAttributeMaxDynamicSharedMemorySize, lstm_smem);
    cudaFuncSetAttribute(gru_rec,  cudaFuncAttributeMaxDynamicSharedMemorySize, gru_smem);

    // 1) vocab projection table (34.6 GFLOP)
    gemm_k<2><<<dim3((VV + 127) / 128, 4), 256>>>(emb, lWihF, lWihB, lbihF, lbihB);
    // 2) LSTM recurrence with P-table gather (grid 128 = single wave)
    lstm_rec<<<2 * (BB / 64), 512, lstm_smem>>>(tokens, lWhhF, lbhhF, lWhhB, lbhhB);
    // 3) GRU input projection (24.8 GFLOP)
    gemm_k<1><<<dim3(RR / 128, 3), 256>>>(nullptr, gWihF, gWihB, gbihF, gbihB);
    // 4) GRU recurrence
    gru_rec<<<2 * (BB / 64), 512, gru_smem>>>(gWhhF, gbhhF, gWhhB, gbhhB);
    // 5) epilogue
    final_kernel<<<BB, 128>>>(fin, attnw, attnb, linW, linb,
                              gamma, beta, mean, var, outW, outb, out);
}

// round 4
// speedup vs baseline: 3.7280x; 1.7292x over previous
#include <cuda_runtime.h>
#include <math.h>

#define BB 4096
#define TT 70
#define EE 300
#define HH 60
#define VV 120000
#define RR (BB*TT)   // 286720 rows

// ---------------- scratch (static device memory; no allocations) ----------------
__device__ float g_proj  [(size_t)VV*480];       // P[v][480] = emb[v] @ [WihF;WihB]^T + bih
__device__ float g_h_lstm[(size_t)RR*120 + 64];  // [T][B][120] (pad for vector tails)
__device__ float g_gi_gru[(size_t)RR*360];       // [T][B][360]
__device__ float g_h_gru [(size_t)RR*120];       // [B][T][120]
__device__ float g_ghf   [BB*HH];
__device__ float g_ghb   [BB*HH];

__device__ __forceinline__ float sigf(float x) { return 1.f / (1.f + __expf(-x)); }

__device__ __forceinline__ unsigned f2tf32(float x) {
    unsigned r;
    asm("cvt.rna.tf32.f32 %0, %1;" : "=r"(r) : "f"(x));
    return r;
}
__device__ __forceinline__ void mma_tf32(float* d, const unsigned* a, const unsigned* b) {
    asm volatile(
        "mma.sync.aligned.m16n8k8.row.col.f32.tf32.tf32.f32 "
        "{%0,%1,%2,%3}, {%4,%5,%6,%7}, {%8,%9}, {%0,%1,%2,%3};"
        : "+f"(d[0]), "+f"(d[1]), "+f"(d[2]), "+f"(d[3])
        : "r"(a[0]), "r"(a[1]), "r"(a[2]), "r"(a[3]), "r"(b[0]), "r"(b[1]));
}

// ---------------- tensor-core GEMM (split-TF32): C[r][n] = sum_k A[r][k]*W[n][k] + bias[n]
// 128x128x32 block tile, 256 threads (8 warps, warp tile 32x64)
// MODE 1: A = g_h_lstm (K=120, M=RR), W = [gru_Wih_f; gru_Wih_b] (N=360) -> g_gi_gru
// MODE 2: A = emb (K=300, M=VV),      W = [lstm_Wih_f; lstm_Wih_b] (N=480) -> g_proj
template<int MODE>
__global__ __launch_bounds__(256) void gemm_tc(
    const float* __restrict__ Ain,
    const float* __restrict__ W0, const float* __restrict__ W1,
    const float* __restrict__ bias0, const float* __restrict__ bias1)
{
    constexpr int N  = (MODE == 2) ? 480 : 360;
    constexpr int K  = (MODE == 2) ? 300 : 120;
    constexpr int NS = (MODE == 2) ? 240 : 180;
    constexpr int M  = (MODE == 2) ? VV  : RR;
    constexpr int TM = 128, TN = 128, TK = 32, RS = 36;

    extern __shared__ unsigned smem_u[];
    unsigned* AH = smem_u;            // [TM*RS]
    unsigned* AL = AH + TM * RS;
    unsigned* BH = AL + TM * RS;
    unsigned* BL = BH + TN * RS;
    __shared__ int rbase[TM];

    float* __restrict__ C = (MODE == 2) ? g_proj : g_gi_gru;
    const float* __restrict__ A = (MODE == 2) ? Ain : (const float*)g_h_lstm;

    const int m0 = blockIdx.x * TM;
    const int n0 = blockIdx.y * TN;
    const int tid = threadIdx.x;
    const int lane = tid & 31, warp = tid >> 5;
    const int gid = lane >> 2, tig = lane & 3;
    const int wm = (warp >> 1) * 32, wn = (warp & 1) * 64;

    for (int i = tid; i < TM; i += 256) {
        int r = m0 + i;
        if (r >= M) r = M - 1;
        rbase[i] = r * K;
    }
    __syncthreads();

    float d[2][8][4];
    #pragma unroll
    for (int mi = 0; mi < 2; mi++)
        #pragma unroll
        for (int ni = 0; ni < 8; ni++)
            #pragma unroll
            for (int q = 0; q < 4; q++) d[mi][ni][q] = 0.f;

    for (int k0 = 0; k0 < K; k0 += TK) {
        const bool fullk = (k0 + TK <= K);
        // ---- stage A: row = tid/2, 16 consecutive k per thread ----
        {
            int row = tid >> 1, ks = (tid & 1) * 16;
            unsigned* ah = AH + row * RS + ks;
            unsigned* al = AL + row * RS + ks;
            const float* ap = A + rbase[row] + k0 + ks;
            if (fullk) {
                #pragma unroll
                for (int q = 0; q < 4; q++) {
                    float4 v = *(const float4*)(ap + q * 4);
                    float xs[4] = {v.x, v.y, v.z, v.w};
                    #pragma unroll
                    for (int e = 0; e < 4; e++) {
                        unsigned hi = f2tf32(xs[e]);
                        ah[q * 4 + e] = hi;
                        al[q * 4 + e] = f2tf32(xs[e] - __uint_as_float(hi));
                    }
                }
            } else {
                #pragma unroll
                for (int e = 0; e < 16; e++) {
                    int kk = k0 + ks + e;
                    float x = (kk < K) ? A[rbase[row] + kk] : 0.f;
                    unsigned hi = f2tf32(x);
                    ah[e] = hi;
                    al[e] = f2tf32(x - __uint_as_float(hi));
                }
            }
        }
        // ---- stage B ----
        {
            int nrow = tid >> 1, ks = (tid & 1) * 16;
            int ng = n0 + nrow;
            unsigned* bh = BH + nrow * RS + ks;
            unsigned* bl = BL + nrow * RS + ks;
            if (ng < N && fullk) {
                const float* wp = (ng < NS) ? (W0 + (size_t)ng * K)
                                            : (W1 + (size_t)(ng - NS) * K);
                #pragma unroll
                for (int q = 0; q < 4; q++) {
                    float4 v = *(const float4*)(wp + k0 + ks + q * 4);
                    float xs[4] = {v.x, v.y, v.z, v.w};
                    #pragma unroll
                    for (int e = 0; e < 4; e++) {
                        unsigned hi = f2tf32(xs[e]);
                        bh[q * 4 + e] = hi;
                        bl[q * 4 + e] = f2tf32(xs[e] - __uint_as_float(hi));
                    }
                }
            } else {
                const float* wp = (ng < NS) ? (W0 + (size_t)ng * K)
                                 : (ng < N) ? (W1 + (size_t)(ng - NS) * K) : nullptr;
                #pragma unroll
                for (int e = 0; e < 16; e++) {
                    int kk = k0 + ks + e;
                    float x = (wp && kk < K) ? wp[kk] : 0.f;
                    unsigned hi = f2tf32(x);
                    bh[e] = hi;
                    bl[e] = f2tf32(x - __uint_as_float(hi));
                }
            }
        }
        __syncthreads();

        #pragma unroll
        for (int kq = 0; kq < 4; kq++) {
            unsigned ah[2][4], al[2][4];
            #pragma unroll
            for (int mi = 0; mi < 2; mi++) {
                int base = (wm + mi * 16 + gid) * RS + kq * 8 + tig;
                ah[mi][0] = AH[base];          ah[mi][1] = AH[base + 8 * RS];
                ah[mi][2] = AH[base + 4];      ah[mi][3] = AH[base + 8 * RS + 4];
                al[mi][0] = AL[base];          al[mi][1] = AL[base + 8 * RS];
                al[mi][2] = AL[base + 4];      al[mi][3] = AL[base + 8 * RS + 4];
            }
            #pragma unroll
            for (int ni = 0; ni < 8; ni++) {
                int bbase = (wn + ni * 8 + gid) * RS + kq * 8 + tig;
                unsigned bh[2] = {BH[bbase], BH[bbase + 4]};
                unsigned bl[2] = {BL[bbase], BL[bbase + 4]};
                #pragma unroll
                for (int mi = 0; mi < 2; mi++) {
                    mma_tf32(d[mi][ni], ah[mi], bh);   // hi*hi
                    mma_tf32(d[mi][ni], al[mi], bh);   // lo*hi
                    mma_tf32(d[mi][ni], ah[mi], bl);   // hi*lo
                }
            }
        }
        __syncthreads();
    }

    // ---- epilogue: bias + float2 stores ----
    #pragma unroll
    for (int mi = 0; mi < 2; mi++) {
        #pragma unroll
        for (int half = 0; half < 2; half++) {
            int mg = m0 + wm + mi * 16 + gid + half * 8;
            if (mg >= M) continue;
            float* crow = C + (size_t)mg * N;
            #pragma unroll
            for (int ni = 0; ni < 8; ni++) {
                int col = n0 + wn + ni * 8 + 2 * tig;
                if (col >= N) continue;
                float b0v = (col     < NS) ? bias0[col]          : bias1[col - NS];
                float b1v = (col + 1 < NS) ? bias0[col + 1]      : bias1[col + 1 - NS];
                float2 v = make_float2(d[mi][ni][half * 2 + 0] + b0v,
                                       d[mi][ni][half * 2 + 1] + b1v);
                *(float2*)(crow + col) = v;
            }
        }
    }
}

// ---------------- LSTM recurrence: 64-batch tiles, 512 threads, regs cell state,
//                  ping-pong h buffer (1 sync/step), prefetched gate inputs ----------------
__global__ __launch_bounds__(512, 1) void lstm_rec(
    const int* __restrict__ tokens,
    const float* __restrict__ WhhF, const float* __restrict__ bhhF,
    const float* __restrict__ WhhB, const float* __restrict__ bhhB)
{
    extern __shared__ float sm[];
    float* Wsh = sm;                    // [60][60*4]: Wsh[j*240 + h*4 + gate]
    float* hsh = Wsh + 60 * 240;        // [2][60][68]
    int*   tsh = (int*)(hsh + 2 * 60 * 68); // [64][70]

    const int dir = blockIdx.x & 1;
    const int b0 = (blockIdx.x >> 1) * 64;
    const float* __restrict__ Whh = dir ? WhhB : WhhF;
    const float* __restrict__ bhh = dir ? bhhB : bhhF;
    const int tid = threadIdx.x;

    for (int i = tid; i < 240 * 60; i += 512) {
        int row = i / 60, j = i - row * 60;   // row = gate*60+h
        int gate = row / 60, h = row - gate * 60;
        Wsh[j * 240 + h * 4 + gate] = Whh[i];
    }
    for (int i = tid; i < 60 * 68; i += 512) hsh[i] = 0.f;
    for (int i = tid; i < 64 * TT; i += 512) tsh[i] = tokens[b0 * TT + i];

    const bool active = tid < 480;
    const int h = tid % 60;
    const int bg = tid / 60;
    float bI = 0, bF = 0, bG = 0, bO = 0;
    if (active) { bI = bhh[h]; bF = bhh[60 + h]; bG = bhh[120 + h]; bO = bhh[180 + h]; }
    float c[8];
    #pragma unroll
    for (int b2 = 0; b2 < 8; b2++) c[b2] = 0.f;
    __syncthreads();

    for (int s = 0; s < TT; s++) {
        const int t = dir ? (TT - 1 - s) : s;
        float* hcur = hsh + (s & 1) * 4080;
        float* hnxt = hsh + ((s + 1) & 1) * 4080;
        if (active) {
            // prefetch gate inputs (independent LDGs, hidden behind j-loop)
            float giI[8], giF[8], giG[8], giO[8];
            #pragma unroll
            for (int b2 = 0; b2 < 8; b2++) {
                int tok = tsh[(bg * 8 + b2) * TT + t];
                const float* gp = g_proj + (size_t)tok * 480 + dir * 240;
                giI[b2] = gp[h]; giF[b2] = gp[60 + h];
                giG[b2] = gp[120 + h]; giO[b2] = gp[180 + h];
            }
            float aI[8], aF[8], aG[8], aO[8];
            #pragma unroll
            for (int b2 = 0; b2 < 8; b2++) { aI[b2] = 0; aF[b2] = 0; aG[b2] = 0; aO[b2] = 0; }
            #pragma unroll 10
            for (int j = 0; j < 60; j++) {
                float4 w = *(const float4*)&Wsh[j * 240 + h * 4];
                float4 h0 = *(const float4*)&hcur[j * 68 + bg * 8];
                float4 h1 = *(const float4*)&hcur[j * 68 + bg * 8 + 4];
                float hv[8] = {h0.x, h0.y, h0.z, h0.w, h1.x, h1.y, h1.z, h1.w};
                #pragma unroll
                for (int b2 = 0; b2 < 8; b2++) {
                    aI[b2] = fmaf(w.x, hv[b2], aI[b2]);
                    aF[b2] = fmaf(w.y, hv[b2], aF[b2]);
                    aG[b2] = fmaf(w.z, hv[b2], aG[b2]);
                    aO[b2] = fmaf(w.w, hv[b2], aO[b2]);
                }
            }
            #pragma unroll
            for (int b2 = 0; b2 < 8; b2++) {
                int bl = bg * 8 + b2;
                float iv = sigf(giI[b2] + aI[b2] + bI);
                float fv = sigf(giF[b2] + aF[b2] + bF);
                float gv = tanhf(giG[b2] + aG[b2] + bG);
                float ov = sigf(giO[b2] + aO[b2] + bO);
                float cc = fmaf(fv, c[b2], iv * gv);
                c[b2] = cc;
                float hv = ov * tanhf(cc);
                hnxt[h * 68 + bl] = hv;
                g_h_lstm[((size_t)t * BB + b0 + bl) * 120 + dir * 60 + h] = hv;
            }
        }
        __syncthreads();
    }
}

// ---------------- GRU recurrence: same structure ----------------
__global__ __launch_bounds__(512, 1) void gru_rec(
    const float* __restrict__ WhhF, const float* __restrict__ bhhF,
    const float* __restrict__ WhhB, const float* __restrict__ bhhB)
{
    extern __shared__ float sm[];
    float* Wsh = sm;                    // [60][60*4] (gate 3 = pad)
    float* hsh = Wsh + 60 * 240;        // [2][60][68]

    const int dir = blockIdx.x & 1;
    const int b0 = (blockIdx.x >> 1) * 64;
    const float* __restrict__ Whh = dir ? WhhB : WhhF;
    const float* __restrict__ bhh = dir ? bhhB : bhhF;
    const int tid = threadIdx.x;

    for (int i = tid; i < 180 * 60; i += 512) {
        int row = i / 60, j = i - row * 60;
        int gate = row / 60, h = row - gate * 60;
        Wsh[j * 240 + h * 4 + gate] = Whh[i];
    }
    for (int i = tid; i < 60 * 68; i += 512) hsh[i] = 0.f;

    const bool active = tid < 480;
    const int h = tid % 60;
    const int bg = tid / 60;
    float bR = 0, bZ = 0, bN = 0;
    if (active) { bR = bhh[h]; bZ = bhh[60 + h]; bN = bhh[120 + h]; }
    float hp[8];
    #pragma unroll
    for (int b2 = 0; b2 < 8; b2++) hp[b2] = 0.f;
    __syncthreads();

    for (int s = 0; s < TT; s++) {
        const int t = dir ? (TT - 1 - s) : s;
        float* hcur = hsh + (s & 1) * 4080;
        float* hnxt = hsh + ((s + 1) & 1) * 4080;
        if (active) {
            float giR[8], giZ[8], giN[8];
            #pragma unroll
            for (int b2 = 0; b2 < 8; b2++) {
                const float* gp = g_gi_gru + ((size_t)t * BB + b0 + bg * 8 + b2) * 360 + dir * 180;
                giR[b2] = gp[h]; giZ[b2] = gp[60 + h]; giN[b2] = gp[120 + h];
            }
            float aR[8], aZ[8], aN[8];
            #pragma unroll
            for (int b2 = 0; b2 < 8; b2++) { aR[b2] = 0; aZ[b2] = 0; aN[b2] = 0; }
            #pragma unroll 10
            for (int j = 0; j < 60; j++) {
                float4 w = *(const float4*)&Wsh[j * 240 + h * 4];
                float4 h0 = *(const float4*)&hcur[j * 68 + bg * 8];
                float4 h1 = *(const float4*)&hcur[j * 68 + bg * 8 + 4];
                float hv[8] = {h0.x, h0.y, h0.z, h0.w, h1.x, h1.y, h1.z, h1.w};
                #pragma unroll
                for (int b2 = 0; b2 < 8; b2++) {
                    aR[b2] = fmaf(w.x, hv[b2], aR[b2]);
                    aZ[b2] = fmaf(w.y, hv[b2], aZ[b2]);
                    aN[b2] = fmaf(w.z, hv[b2], aN[b2]);
                }
            }
            #pragma unroll
            for (int b2 = 0; b2 < 8; b2++) {
                int bl = bg * 8 + b2;
                int bgl = b0 + bl;
                float r = sigf(giR[b2] + aR[b2] + bR);
                float z = sigf(giZ[b2] + aZ[b2] + bZ);
                float n = tanhf(giN[b2] + r * (aN[b2] + bN));
                float hv = (1.f - z) * n + z * hp[b2];
                hp[b2] = hv;
                hnxt[h * 68 + bl] = hv;
                g_h_gru[(size_t)bgl * TT * 120 + t * 120 + dir * 60 + h] = hv;
                if (s == TT - 1) {
                    if (dir) g_ghb[bgl * 60 + h] = hv;
                    else     g_ghf[bgl * 60 + h] = hv;
                }
            }
        }
        __syncthreads();
    }
}

// ---------------- final: attention + pools + linear + BN + out ----------------
__global__ __launch_bounds__(128) void final_kernel(
    const float* __restrict__ fin,
    const float* __restrict__ attn_w, const float* __restrict__ attn_b,
    const float* __restrict__ linW, const float* __restrict__ linb,
    const float* __restrict__ gamma, const float* __restrict__ beta,
    const float* __restrict__ mean, const float* __restrict__ var,
    const float* __restrict__ outW, const float* __restrict__ outb,
    float* __restrict__ out)
{
    __shared__ float hs[TT * 120];
    __shared__ float att[TT];
    __shared__ float conc[484];
    __shared__ float o16[16];
    __shared__ float asum_s;

    const int b = blockIdx.x;
    const int tid = threadIdx.x;
    const float* hp = g_h_gru + (size_t)b * TT * 120;

    for (int i = tid; i < TT * 120; i += 128) hs[i] = hp[i];
    __syncthreads();

    const int warp = tid >> 5, lane = tid & 31;
    for (int t = warp; t < TT; t += 4) {
        float s = 0.f;
        for (int k = lane; k < 120; k += 32) s = fmaf(hs[t * 120 + k], attn_w[k], s);
        #pragma unroll
        for (int o = 16; o > 0; o >>= 1) s += __shfl_xor_sync(0xffffffffu, s, o);
        if (lane == 0) att[t] = expf(tanhf(s) + attn_b[t]);
    }
    __syncthreads();
    if (tid == 0) {
        float s = 0.f;
        for (int t = 0; t < TT; t++) s += att[t];
        asum_s = s + 1e-10f;
    }
    __syncthreads();
    const float inva = 1.f / asum_s;

    if (tid < 120) {
        const int fidx = tid;
        float hat = 0.f, avg = 0.f, mx = -INFINITY;
        for (int t = 0; t < TT; t++) {
            float v = hs[t * 120 + fidx];
            hat = fmaf(v, att[t], hat);
            avg += v;
            mx = fmaxf(mx, v);
        }
        conc[120 + fidx] = hat * inva;
        conc[240 + fidx] = avg * (1.f / (float)TT);
        conc[360 + fidx] = mx;
        float hhv;
        int sub = (fidx >= 60) ? 1 : 0;
        int col = fidx - sub * 60;
        if (b < BB / 2) hhv = g_ghf[(2 * b + sub) * 60 + col];
        else            hhv = g_ghb[(2 * (b - BB / 2) + sub) * 60 + col];
        conc[fidx] = hhv;
    }
    if (tid == 0) conc[480] = fin[b];
    __syncthreads();

    if (tid < 16) {
        float s = linb[tid];
        const float* w = linW + tid * 481;
        for (int k = 0; k < 481; k++) s = fmaf(w[k], conc[k], s);
        s = fmaxf(s, 0.f);
        s = (s - mean[tid]) * rsqrtf(var[tid] + 1e-5f) * gamma[tid] + beta[tid];
        o16[tid] = s;
    }
    __syncthreads();
    if (tid == 0) {
        float s = outb[0];
        #pragma unroll
        for (int k = 0; k < 16; k++) s = fmaf(outW[k], o16[k], s);
        out[b] = s;
    }
}

// ---------------- launch ----------------
extern "C" void kernel_launch(void* const* d_in, const int* in_sizes, int n_in,
                              void* d_out, int out_size)
{
    const int*   tokens = (const int*)  d_in[0];
    const float* fin    = (const float*)d_in[1];
    const float* emb    = (const float*)d_in[2];
    const float* lWihF  = (const float*)d_in[3];
    const float* lWhhF  = (const float*)d_in[4];
    const float* lbihF  = (const float*)d_in[5];
    const float* lbhhF  = (const float*)d_in[6];
    const float* lWihB  = (const float*)d_in[7];
    const float* lWhhB  = (const float*)d_in[8];
    const float* lbihB  = (const float*)d_in[9];
    const float* lbhhB  = (const float*)d_in[10];
    const float* gWihF  = (const float*)d_in[11];
    const float* gWhhF  = (const float*)d_in[12];
    const float* gbihF  = (const float*)d_in[13];
    const float* gbhhF  = (const float*)d_in[14];
    const float* gWihB  = (const float*)d_in[15];
    const float* gWhhB  = (const float*)d_in[16];
    const float* gbihB  = (const float*)d_in[17];
    const float* gbhhB  = (const float*)d_in[18];
    const float* attnw  = (const float*)d_in[19];
    const float* attnb  = (const float*)d_in[20];
    const float* linW   = (const float*)d_in[21];
    const float* linb   = (const float*)d_in[22];
    const float* gamma  = (const float*)d_in[23];
    const float* beta   = (const float*)d_in[24];
    const float* mean   = (const float*)d_in[25];
    const float* var    = (const float*)d_in[26];
    const float* outW   = (const float*)d_in[27];
    const float* outb   = (const float*)d_in[28];
    float* out = (float*)d_out;

    const int gemm_smem = 4 * 128 * 36 * 4;                        // 73728 B
    const int lstm_smem = (60*240 + 2*60*68) * 4 + 64*TT*4;        // 108160 B
    const int gru_smem  = (60*240 + 2*60*68) * 4;                  // 90240 B
    cudaFuncSetAttribute(gemm_tc<2>, cudaFuncAttributeMaxDynamicSharedMemorySize, gemm_smem);
    cudaFuncSetAttribute(gemm_tc<1>, cudaFuncAttributeMaxDynamicSharedMemorySize, gemm_smem);
    cudaFuncSetAttribute(lstm_rec, cudaFuncAttributeMaxDynamicSharedMemorySize, lstm_smem);
    cudaFuncSetAttribute(gru_rec,  cudaFuncAttributeMaxDynamicSharedMemorySize, gru_smem);

    // 1) vocab projection table (tensor cores, split-tf32)
    gemm_tc<2><<<dim3((VV + 127) / 128, 4), 256, gemm_smem>>>(emb, lWihF, lWihB, lbihF, lbihB);
    // 2) LSTM recurrence with P-table gather
    lstm_rec<<<2 * (BB / 64), 512, lstm_smem>>>(tokens, lWhhF, lbhhF, lWhhB, lbhhB);
    // 3) GRU input projection (tensor cores, split-tf32)
    gemm_tc<1><<<dim3(RR / 128, 3), 256, gemm_smem>>>(nullptr, gWihF, gWihB, gbihF, gbihB);
    // 4) GRU recurrence
    gru_rec<<<2 * (BB / 64), 512, gru_smem>>>(gWhhF, gbhhF, gWhhB, gbhhB);
    // 5) epilogue
    final_kernel<<<BB, 128>>>(fin, attnw, attnb, linW, linb,
                              gamma, beta, mean, var, outW, outb, out);
}

// round 5
// speedup vs baseline: 3.7740x; 1.0124x over previous
#include <cuda_runtime.h>
#include <math.h>

#define BB 4096
#define TT 70
#define EE 300
#define HH 60
#define VV 120000
#define RR (BB*TT)   // 286720 rows

typedef unsigned long long ull;

// ---------------- scratch (static device memory; no allocations) ----------------
__device__ float g_proj  [(size_t)VV*480];       // P[v][480] = emb[v] @ [WihF;WihB]^T + bih
__device__ float g_h_lstm[(size_t)RR*120 + 64];  // [T][B][120]
__device__ float g_gi_gru[(size_t)RR*360];       // [T][B][360]
__device__ float g_h_gru [(size_t)RR*120];       // [B][T][120]
__device__ float g_ghf   [BB*HH];
__device__ float g_ghb   [BB*HH];

__device__ __forceinline__ float sigf(float x) { return 1.f / (1.f + __expf(-x)); }

__device__ __forceinline__ unsigned f2tf32(float x) {
    unsigned r;
    asm("cvt.rna.tf32.f32 %0, %1;" : "=r"(r) : "f"(x));
    return r;
}
__device__ __forceinline__ void mma_tf32(float* d, const unsigned* a, const unsigned* b) {
    asm volatile(
        "mma.sync.aligned.m16n8k8.row.col.f32.tf32.tf32.f32 "
        "{%0,%1,%2,%3}, {%4,%5,%6,%7}, {%8,%9}, {%0,%1,%2,%3};"
        : "+f"(d[0]), "+f"(d[1]), "+f"(d[2]), "+f"(d[3])
        : "r"(a[0]), "r"(a[1]), "r"(a[2]), "r"(a[3]), "r"(b[0]), "r"(b[1]));
}

// ---- packed f32x2 helpers (Blackwell) ----
__device__ __forceinline__ void fma2(ull& d, ull a, ull b) {
    asm("fma.rn.f32x2 %0, %1, %2, %0;" : "+l"(d) : "l"(a), "l"(b));
}
__device__ __forceinline__ ull dup2(float x) {
    ull r;
    unsigned u = __float_as_uint(x);
    asm("mov.b64 %0, {%1, %1};" : "=l"(r) : "r"(u));
    return r;
}
__device__ __forceinline__ float2 unpk2(ull v) {
    unsigned lo, hi;
    asm("mov.b64 {%0, %1}, %2;" : "=r"(lo), "=r"(hi) : "l"(v));
    return make_float2(__uint_as_float(lo), __uint_as_float(hi));
}

// ---------------- tensor-core GEMM (split-TF32) ----------------
template<int MODE>
__global__ __launch_bounds__(256) void gemm_tc(
    const float* __restrict__ Ain,
    const float* __restrict__ W0, const float* __restrict__ W1,
    const float* __restrict__ bias0, const float* __restrict__ bias1)
{
    constexpr int N  = (MODE == 2) ? 480 : 360;
    constexpr int K  = (MODE == 2) ? 300 : 120;
    constexpr int NS = (MODE == 2) ? 240 : 180;
    constexpr int M  = (MODE == 2) ? VV  : RR;
    constexpr int TM = 128, TN = 128, TK = 32, RS = 36;

    extern __shared__ unsigned smem_u[];
    unsigned* AH = smem_u;
    unsigned* AL = AH + TM * RS;
    unsigned* BH = AL + TM * RS;
    unsigned* BL = BH + TN * RS;
    __shared__ int rbase[TM];

    float* __restrict__ C = (MODE == 2) ? g_proj : g_gi_gru;
    const float* __restrict__ A = (MODE == 2) ? Ain : (const float*)g_h_lstm;

    const int m0 = blockIdx.x * TM;
    const int n0 = blockIdx.y * TN;
    const int tid = threadIdx.x;
    const int lane = tid & 31, warp = tid >> 5;
    const int gid = lane >> 2, tig = lane & 3;
    const int wm = (warp >> 1) * 32, wn = (warp & 1) * 64;

    for (int i = tid; i < TM; i += 256) {
        int r = m0 + i;
        if (r >= M) r = M - 1;
        rbase[i] = r * K;
    }
    __syncthreads();

    float d[2][8][4];
    #pragma unroll
    for (int mi = 0; mi < 2; mi++)
        #pragma unroll
        for (int ni = 0; ni < 8; ni++)
            #pragma unroll
            for (int q = 0; q < 4; q++) d[mi][ni][q] = 0.f;

    for (int k0 = 0; k0 < K; k0 += TK) {
        const bool fullk = (k0 + TK <= K);
        {
            int row = tid >> 1, ks = (tid & 1) * 16;
            unsigned* ah = AH + row * RS + ks;
            unsigned* al = AL + row * RS + ks;
            const float* ap = A + rbase[row] + k0 + ks;
            if (fullk) {
                #pragma unroll
                for (int q = 0; q < 4; q++) {
                    float4 v = *(const float4*)(ap + q * 4);
                    float xs[4] = {v.x, v.y, v.z, v.w};
                    #pragma unroll
                    for (int e = 0; e < 4; e++) {
                        unsigned hi = f2tf32(xs[e]);
                        ah[q * 4 + e] = hi;
                        al[q * 4 + e] = f2tf32(xs[e] - __uint_as_float(hi));
                    }
                }
            } else {
                #pragma unroll
                for (int e = 0; e < 16; e++) {
                    int kk = k0 + ks + e;
                    float x = (kk < K) ? A[rbase[row] + kk] : 0.f;
                    unsigned hi = f2tf32(x);
                    ah[e] = hi;
                    al[e] = f2tf32(x - __uint_as_float(hi));
                }
            }
        }
        {
            int nrow = tid >> 1, ks = (tid & 1) * 16;
            int ng = n0 + nrow;
            unsigned* bh = BH + nrow * RS + ks;
            unsigned* bl = BL + nrow * RS + ks;
            if (ng < N && fullk) {
                const float* wp = (ng < NS) ? (W0 + (size_t)ng * K)
                                            : (W1 + (size_t)(ng - NS) * K);
                #pragma unroll
                for (int q = 0; q < 4; q++) {
                    float4 v = *(const float4*)(wp + k0 + ks + q * 4);
                    float xs[4] = {v.x, v.y, v.z, v.w};
                    #pragma unroll
                    for (int e = 0; e < 4; e++) {
                        unsigned hi = f2tf32(xs[e]);
                        bh[q * 4 + e] = hi;
                        bl[q * 4 + e] = f2tf32(xs[e] - __uint_as_float(hi));
                    }
                }
            } else {
                const float* wp = (ng < NS) ? (W0 + (size_t)ng * K)
                                 : (ng < N) ? (W1 + (size_t)(ng - NS) * K) : nullptr;
                #pragma unroll
                for (int e = 0; e < 16; e++) {
                    int kk = k0 + ks + e;
                    float x = (wp && kk < K) ? wp[kk] : 0.f;
                    unsigned hi = f2tf32(x);
                    bh[e] = hi;
                    bl[e] = f2tf32(x - __uint_as_float(hi));
                }
            }
        }
        __syncthreads();

        #pragma unroll
        for (int kq = 0; kq < 4; kq++) {
            unsigned ah[2][4], al[2][4];
            #pragma unroll
            for (int mi = 0; mi < 2; mi++) {
                int base = (wm + mi * 16 + gid) * RS + kq * 8 + tig;
                ah[mi][0] = AH[base];          ah[mi][1] = AH[base + 8 * RS];
                ah[mi][2] = AH[base + 4];      ah[mi][3] = AH[base + 8 * RS + 4];
                al[mi][0] = AL[base];          al[mi][1] = AL[base + 8 * RS];
                al[mi][2] = AL[base + 4];      al[mi][3] = AL[base + 8 * RS + 4];
            }
            #pragma unroll
            for (int ni = 0; ni < 8; ni++) {
                int bbase = (wn + ni * 8 + gid) * RS + kq * 8 + tig;
                unsigned bh[2] = {BH[bbase], BH[bbase + 4]};
                unsigned bl[2] = {BL[bbase], BL[bbase + 4]};
                #pragma unroll
                for (int mi = 0; mi < 2; mi++) {
                    mma_tf32(d[mi][ni], ah[mi], bh);
                    mma_tf32(d[mi][ni], al[mi], bh);
                    mma_tf32(d[mi][ni], ah[mi], bl);
                }
            }
        }
        __syncthreads();
    }

    #pragma unroll
    for (int mi = 0; mi < 2; mi++) {
        #pragma unroll
        for (int half = 0; half < 2; half++) {
            int mg = m0 + wm + mi * 16 + gid + half * 8;
            if (mg >= M) continue;
            float* crow = C + (size_t)mg * N;
            #pragma unroll
            for (int ni = 0; ni < 8; ni++) {
                int col = n0 + wn + ni * 8 + 2 * tig;
                if (col >= N) continue;
                float b0v = (col     < NS) ? bias0[col]     : bias1[col - NS];
                float b1v = (col + 1 < NS) ? bias0[col + 1] : bias1[col + 1 - NS];
                float2 v = make_float2(d[mi][ni][half * 2 + 0] + b0v,
                                       d[mi][ni][half * 2 + 1] + b1v);
                *(float2*)(crow + col) = v;
            }
        }
    }
}

// ---------------- LSTM recurrence: f32x2 packed FMA, regs cell state ----------------
__global__ __launch_bounds__(512, 1) void lstm_rec(
    const int* __restrict__ tokens,
    const float* __restrict__ WhhF, const float* __restrict__ bhhF,
    const float* __restrict__ WhhB, const float* __restrict__ bhhB)
{
    extern __shared__ float sm[];
    float* Wsh = sm;                    // [60][60*4]: Wsh[j*240 + h*4 + gate]
    float* hsh = Wsh + 60 * 240;        // [2][60][68]
    int*   tsh = (int*)(hsh + 2 * 60 * 68);

    const int dir = blockIdx.x & 1;
    const int b0 = (blockIdx.x >> 1) * 64;
    const float* __restrict__ Whh = dir ? WhhB : WhhF;
    const float* __restrict__ bhh = dir ? bhhB : bhhF;
    const int tid = threadIdx.x;

    for (int i = tid; i < 240 * 60; i += 512) {
        int row = i / 60, j = i - row * 60;
        int gate = row / 60, h = row - gate * 60;
        Wsh[j * 240 + h * 4 + gate] = Whh[i];
    }
    for (int i = tid; i < 60 * 68; i += 512) hsh[i] = 0.f;
    for (int i = tid; i < 64 * TT; i += 512) tsh[i] = tokens[b0 * TT + i];

    const bool active = tid < 480;
    const int h = tid % 60;
    const int bg = tid / 60;
    float bI = 0, bF = 0, bG = 0, bO = 0;
    if (active) { bI = bhh[h]; bF = bhh[60 + h]; bG = bhh[120 + h]; bO = bhh[180 + h]; }
    float c[8];
    #pragma unroll
    for (int b2 = 0; b2 < 8; b2++) c[b2] = 0.f;
    __syncthreads();

    for (int s = 0; s < TT; s++) {
        const int t = dir ? (TT - 1 - s) : s;
        float* hcur = hsh + (s & 1) * 4080;
        float* hnxt = hsh + ((s + 1) & 1) * 4080;
        if (active) {
            float giI[8], giF[8], giG[8], giO[8];
            #pragma unroll
            for (int b2 = 0; b2 < 8; b2++) {
                int tok = tsh[(bg * 8 + b2) * TT + t];
                const float* gp = g_proj + (size_t)tok * 480 + dir * 240;
                giI[b2] = gp[h]; giF[b2] = gp[60 + h];
                giG[b2] = gp[120 + h]; giO[b2] = gp[180 + h];
            }
            ull aI[4], aF[4], aG[4], aO[4];
            #pragma unroll
            for (int p = 0; p < 4; p++) { aI[p] = 0; aF[p] = 0; aG[p] = 0; aO[p] = 0; }
            #pragma unroll 10
            for (int j = 0; j < 60; j++) {
                float4 w = *(const float4*)&Wsh[j * 240 + h * 4];
                ull wi = dup2(w.x), wf = dup2(w.y), wg = dup2(w.z), wo = dup2(w.w);
                ulonglong2 hA = *(const ulonglong2*)&hcur[j * 68 + bg * 8];
                ulonglong2 hB = *(const ulonglong2*)&hcur[j * 68 + bg * 8 + 4];
                ull hv[4] = {hA.x, hA.y, hB.x, hB.y};
                #pragma unroll
                for (int p = 0; p < 4; p++) {
                    fma2(aI[p], wi, hv[p]);
                    fma2(aF[p], wf, hv[p]);
                    fma2(aG[p], wg, hv[p]);
                    fma2(aO[p], wo, hv[p]);
                }
            }
            #pragma unroll
            for (int p = 0; p < 4; p++) {
                float2 vI = unpk2(aI[p]), vF = unpk2(aF[p]);
                float2 vG = unpk2(aG[p]), vO = unpk2(aO[p]);
                float aIv[2] = {vI.x, vI.y}, aFv[2] = {vF.x, vF.y};
                float aGv[2] = {vG.x, vG.y}, aOv[2] = {vO.x, vO.y};
                #pragma unroll
                for (int e = 0; e < 2; e++) {
                    int b2 = p * 2 + e;
                    int bl = bg * 8 + b2;
                    float iv = sigf(giI[b2] + aIv[e] + bI);
                    float fv = sigf(giF[b2] + aFv[e] + bF);
                    float gv = tanhf(giG[b2] + aGv[e] + bG);
                    float ov = sigf(giO[b2] + aOv[e] + bO);
                    float cc = fmaf(fv, c[b2], iv * gv);
                    c[b2] = cc;
                    float hv = ov * tanhf(cc);
                    hnxt[h * 68 + bl] = hv;
                    g_h_lstm[((size_t)t * BB + b0 + bl) * 120 + dir * 60 + h] = hv;
                }
            }
        }
        __syncthreads();
    }
}

// ---------------- GRU recurrence: f32x2 packed FMA ----------------
__global__ __launch_bounds__(512, 1) void gru_rec(
    const float* __restrict__ WhhF, const float* __restrict__ bhhF,
    const float* __restrict__ WhhB, const float* __restrict__ bhhB)
{
    extern __shared__ float sm[];
    float* Wsh = sm;                    // [60][60*4] (gate 3 = pad)
    float* hsh = Wsh + 60 * 240;        // [2][60][68]

    const int dir = blockIdx.x & 1;
    const int b0 = (blockIdx.x >> 1) * 64;
    const float* __restrict__ Whh = dir ? WhhB : WhhF;
    const float* __restrict__ bhh = dir ? bhhB : bhhF;
    const int tid = threadIdx.x;

    for (int i = tid; i < 180 * 60; i += 512) {
        int row = i / 60, j = i - row * 60;
        int gate = row / 60, h = row - gate * 60;
        Wsh[j * 240 + h * 4 + gate] = Whh[i];
    }
    for (int i = tid; i < 60 * 68; i += 512) hsh[i] = 0.f;

    const bool active = tid < 480;
    const int h = tid % 60;
    const int bg = tid / 60;
    float bR = 0, bZ = 0, bN = 0;
    if (active) { bR = bhh[h]; bZ = bhh[60 + h]; bN = bhh[120 + h]; }
    float hp[8];
    #pragma unroll
    for (int b2 = 0; b2 < 8; b2++) hp[b2] = 0.f;
    __syncthreads();

    for (int s = 0; s < TT; s++) {
        const int t = dir ? (TT - 1 - s) : s;
        float* hcur = hsh + (s & 1) * 4080;
        float* hnxt = hsh + ((s + 1) & 1) * 4080;
        if (active) {
            float giR[8], giZ[8], giN[8];
            #pragma unroll
            for (int b2 = 0; b2 < 8; b2++) {
                const float* gp = g_gi_gru + ((size_t)t * BB + b0 + bg * 8 + b2) * 360 + dir * 180;
                giR[b2] = gp[h]; giZ[b2] = gp[60 + h]; giN[b2] = gp[120 + h];
            }
            ull aR[4], aZ[4], aN[4];
            #pragma unroll
            for (int p = 0; p < 4; p++) { aR[p] = 0; aZ[p] = 0; aN[p] = 0; }
            #pragma unroll 10
            for (int j = 0; j < 60; j++) {
                float4 w = *(const float4*)&Wsh[j * 240 + h * 4];
                ull wr = dup2(w.x), wz = dup2(w.y), wn = dup2(w.z);
                ulonglong2 hA = *(const ulonglong2*)&hcur[j * 68 + bg * 8];
                ulonglong2 hB = *(const ulonglong2*)&hcur[j * 68 + bg * 8 + 4];
                ull hv[4] = {hA.x, hA.y, hB.x, hB.y};
                #pragma unroll
                for (int p = 0; p < 4; p++) {
                    fma2(aR[p], wr, hv[p]);
                    fma2(aZ[p], wz, hv[p]);
                    fma2(aN[p], wn, hv[p]);
                }
            }
            #pragma unroll
            for (int p = 0; p < 4; p++) {
                float2 vR = unpk2(aR[p]), vZ = unpk2(aZ[p]), vN = unpk2(aN[p]);
                float aRv[2] = {vR.x, vR.y}, aZv[2] = {vZ.x, vZ.y}, aNv[2] = {vN.x, vN.y};
                #pragma unroll
                for (int e = 0; e < 2; e++) {
                    int b2 = p * 2 + e;
                    int bl = bg * 8 + b2;
                    int bgl = b0 + bl;
                    float r = sigf(giR[b2] + aRv[e] + bR);
                    float z = sigf(giZ[b2] + aZv[e] + bZ);
                    float n = tanhf(giN[b2] + r * (aNv[e] + bN));
                    float hv = (1.f - z) * n + z * hp[b2];
                    hp[b2] = hv;
                    hnxt[h * 68 + bl] = hv;
                    g_h_gru[(size_t)bgl * TT * 120 + t * 120 + dir * 60 + h] = hv;
                    if (s == TT - 1) {
                        if (dir) g_ghb[bgl * 60 + h] = hv;
                        else     g_ghf[bgl * 60 + h] = hv;
                    }
                }
            }
        }
        __syncthreads();
    }
}

// ---------------- final: attention + pools + linear + BN + out ----------------
__global__ __launch_bounds__(128) void final_kernel(
    const float* __restrict__ fin,
    const float* __restrict__ attn_w, const float* __restrict__ attn_b,
    const float* __restrict__ linW, const float* __restrict__ linb,
    const float* __restrict__ gamma, const float* __restrict__ beta,
    const float* __restrict__ mean, const float* __restrict__ var,
    const float* __restrict__ outW, const float* __restrict__ outb,
    float* __restrict__ out)
{
    __shared__ float hs[TT * 120];
    __shared__ float att[TT];
    __shared__ float conc[484];
    __shared__ float o16[16];
    __shared__ float asum_s;

    const int b = blockIdx.x;
    const int tid = threadIdx.x;
    const float* hp = g_h_gru + (size_t)b * TT * 120;

    for (int i = tid; i < TT * 120; i += 128) hs[i] = hp[i];
    __syncthreads();

    const int warp = tid >> 5, lane = tid & 31;
    for (int t = warp; t < TT; t += 4) {
        float s = 0.f;
        for (int k = lane; k < 120; k += 32) s = fmaf(hs[t * 120 + k], attn_w[k], s);
        #pragma unroll
        for (int o = 16; o > 0; o >>= 1) s += __shfl_xor_sync(0xffffffffu, s, o);
        if (lane == 0) att[t] = expf(tanhf(s) + attn_b[t]);
    }
    __syncthreads();
    if (tid == 0) {
        float s = 0.f;
        for (int t = 0; t < TT; t++) s += att[t];
        asum_s = s + 1e-10f;
    }
    __syncthreads();
    const float inva = 1.f / asum_s;

    if (tid < 120) {
        const int fidx = tid;
        float hat = 0.f, avg = 0.f, mx = -INFINITY;
        for (int t = 0; t < TT; t++) {
            float v = hs[t * 120 + fidx];
            hat = fmaf(v, att[t], hat);
            avg += v;
            mx = fmaxf(mx, v);
        }
        conc[120 + fidx] = hat * inva;
        conc[240 + fidx] = avg * (1.f / (float)TT);
        conc[360 + fidx] = mx;
        float hhv;
        int sub = (fidx >= 60) ? 1 : 0;
        int col = fidx - sub * 60;
        if (b < BB / 2) hhv = g_ghf[(2 * b + sub) * 60 + col];
        else            hhv = g_ghb[(2 * (b - BB / 2) + sub) * 60 + col];
        conc[fidx] = hhv;
    }
    if (tid == 0) conc[480] = fin[b];
    __syncthreads();

    if (tid < 16) {
        float s = linb[tid];
        const float* w = linW + tid * 481;
        for (int k = 0; k < 481; k++) s = fmaf(w[k], conc[k], s);
        s = fmaxf(s, 0.f);
        s = (s - mean[tid]) * rsqrtf(var[tid] + 1e-5f) * gamma[tid] + beta[tid];
        o16[tid] = s;
    }
    __syncthreads();
    if (tid == 0) {
        float s = outb[0];
        #pragma unroll
        for (int k = 0; k < 16; k++) s = fmaf(outW[k], o16[k], s);
        out[b] = s;
    }
}

// ---------------- launch ----------------
extern "C" void kernel_launch(void* const* d_in, const int* in_sizes, int n_in,
                              void* d_out, int out_size)
{
    const int*   tokens = (const int*)  d_in[0];
    const float* fin    = (const float*)d_in[1];
    const float* emb    = (const float*)d_in[2];
    const float* lWihF  = (const float*)d_in[3];
    const float* lWhhF  = (const float*)d_in[4];
    const float* lbihF  = (const float*)d_in[5];
    const float* lbhhF  = (const float*)d_in[6];
    const float* lWihB  = (const float*)d_in[7];
    const float* lWhhB  = (const float*)d_in[8];
    const float* lbihB  = (const float*)d_in[9];
    const float* lbhhB  = (const float*)d_in[10];
    const float* gWihF  = (const float*)d_in[11];
    const float* gWhhF  = (const float*)d_in[12];
    const float* gbihF  = (const float*)d_in[13];
    const float* gbhhF  = (const float*)d_in[14];
    const float* gWihB  = (const float*)d_in[15];
    const float* gWhhB  = (const float*)d_in[16];
    const float* gbihB  = (const float*)d_in[17];
    const float* gbhhB  = (const float*)d_in[18];
    const float* attnw  = (const float*)d_in[19];
    const float* attnb  = (const float*)d_in[20];
    const float* linW   = (const float*)d_in[21];
    const float* linb   = (const float*)d_in[22];
    const float* gamma  = (const float*)d_in[23];
    const float* beta   = (const float*)d_in[24];
    const float* mean   = (const float*)d_in[25];
    const float* var    = (const float*)d_in[26];
    const float* outW   = (const float*)d_in[27];
    const float* outb   = (const float*)d_in[28];
    float* out = (float*)d_out;

    const int gemm_smem = 4 * 128 * 36 * 4;
    const int lstm_smem = (60*240 + 2*60*68) * 4 + 64*TT*4;
    const int gru_smem  = (60*240 + 2*60*68) * 4;
    cudaFuncSetAttribute(gemm_tc<2>, cudaFuncAttributeMaxDynamicSharedMemorySize, gemm_smem);
    cudaFuncSetAttribute(gemm_tc<1>, cudaFuncAttributeMaxDynamicSharedMemorySize, gemm_smem);
    cudaFuncSetAttribute(lstm_rec, cudaFuncAttributeMaxDynamicSharedMemorySize, lstm_smem);
    cudaFuncSetAttribute(gru_rec,  cudaFuncAttributeMaxDynamicSharedMemorySize, gru_smem);

    gemm_tc<2><<<dim3((VV + 127) / 128, 4), 256, gemm_smem>>>(emb, lWihF, lWihB, lbihF, lbihB);
    lstm_rec<<<2 * (BB / 64), 512, lstm_smem>>>(tokens, lWhhF, lbhhF, lWhhB, lbhhB);
    gemm_tc<1><<<dim3(RR / 128, 3), 256, gemm_smem>>>(nullptr, gWihF, gWihB, gbihF, gbihB);
    gru_rec<<<2 * (BB / 64), 512, gru_smem>>>(gWhhF, gbhhF, gWhhB, gbhhB);
    final_kernel<<<BB, 128>>>(fin, attnw, attnb, linW, linb,
                              gamma, beta, mean, var, outW, outb, out);
}